// round 1
// baseline (speedup 1.0000x reference)
#include <cuda_runtime.h>

#define BB 4
#define CC 256
#define NN 4096
#define NH 8
#define HD 32
#define NA 1024

// Scratch (device globals — no allocations allowed)
__device__ float g_q[16 * 8 * 32 * 1024];   // [ba][h][d][na], pre-scaled by hd^-0.5
__device__ float g_k[16 * 8 * 32 * 1024];   // [ba][h][d][na]
__device__ float g_v[16 * 8 * 32 * 1024];   // [ba][h][d][na]
__device__ float g_vf[4 * 256 * 4096];      // [b][c][n]  (v in NCHW for dwconv)
__device__ float g_tmp[4 * 256 * 4096];     // [b][c][n]  attn out + pe conv

// ---------------------------------------------------------------------------
// Kernel 1: qkv = W_qkv @ x  (per batch: [768,256] x [256,4096]), scatter to
// q/k/v in [ba][h][hd][na] layout (+ v also to NCHW layout).
// grid (4096/64, 768/64, B), block 256.
// ---------------------------------------------------------------------------
__global__ __launch_bounds__(256) void qkv_gemm(const float* __restrict__ x,
                                                const float* __restrict__ w,
                                                const float* __restrict__ bias) {
    __shared__ float Ws[16][64];  // [k][o]
    __shared__ float Xs[16][64];  // [k][n]
    const int nBase = blockIdx.x * 64;
    const int oBase = blockIdx.y * 64;
    const int b = blockIdx.z;
    const int t = threadIdx.x;
    const int tx = t & 15, ty = t >> 4;
    const float* xb = x + (size_t)b * CC * NN;
    float acc[4][4] = {};
    const int wo = t >> 2, wk = (t & 3) * 4;
    const int xk = t >> 4, xn = (t & 15) * 4;
    for (int c0 = 0; c0 < CC; c0 += 16) {
        float4 wv = *(const float4*)&w[(size_t)(oBase + wo) * CC + c0 + wk];
        Ws[wk + 0][wo] = wv.x; Ws[wk + 1][wo] = wv.y;
        Ws[wk + 2][wo] = wv.z; Ws[wk + 3][wo] = wv.w;
        *(float4*)&Xs[xk][xn] = *(const float4*)&xb[(size_t)(c0 + xk) * NN + nBase + xn];
        __syncthreads();
#pragma unroll
        for (int kk = 0; kk < 16; kk++) {
            float4 av = *(const float4*)&Ws[kk][ty * 4];
            float4 bv = *(const float4*)&Xs[kk][tx * 4];
            float a[4] = {av.x, av.y, av.z, av.w};
            float bb2[4] = {bv.x, bv.y, bv.z, bv.w};
#pragma unroll
            for (int i = 0; i < 4; i++)
#pragma unroll
                for (int j = 0; j < 4; j++)
                    acc[i][j] += a[i] * bb2[j];
        }
        __syncthreads();
    }
    const int n0 = nBase + tx * 4;
    const int ba = b * 4 + (n0 >> 10);
    const int na = n0 & 1023;
#pragma unroll
    for (int i = 0; i < 4; i++) {
        int o = oBase + ty * 4 + i;
        int h = o / 96, rem = o % 96;
        int typ = rem >> 5, d = rem & 31;
        float bo = bias[o];
        float4 v4 = make_float4(acc[i][0] + bo, acc[i][1] + bo,
                                acc[i][2] + bo, acc[i][3] + bo);
        size_t idx = (((size_t)(ba * 8 + h) * 32 + d) << 10) + na;
        if (typ == 0) {
            const float s = 0.17677669529663687f;  // 32^-0.5
            v4.x *= s; v4.y *= s; v4.z *= s; v4.w *= s;
            *(float4*)&g_q[idx] = v4;
        } else if (typ == 1) {
            *(float4*)&g_k[idx] = v4;
        } else {
            *(float4*)&g_v[idx] = v4;
            *(float4*)&g_vf[(((size_t)b * 256 + h * 32 + d) << 12) + n0] = v4;
        }
    }
}

// ---------------------------------------------------------------------------
// Kernel 2: flash attention per (row-tile 64, head, ba). Block 128 threads.
// Online softmax; P staged through smem; output to g_tmp[B,C,N] coalesced.
// grid (1024/64, 8, 16).
// ---------------------------------------------------------------------------
__global__ __launch_bounds__(128) void attn_kernel() {
    __shared__ float Qs[64][36];  // [i][d]
    __shared__ float Ks[64][36];  // [j][d]
    __shared__ float Vs[64][36];  // [j][d]
    __shared__ float Ps[64][76];  // P tile; reused as O^T [32][64] at the end
    const int i0 = blockIdx.x * 64;
    const int h = blockIdx.y;
    const int ba = blockIdx.z;
    const int t = threadIdx.x;
    const int rg = t >> 3;   // row group: owns rows rg*4 .. rg*4+3
    const int cc = t & 7;    // col group: owns S cols cc*8.., O cols cc*4..
    const size_t bh = (size_t)(ba * 8 + h) * (32 * 1024);
    const float* qb = g_q + bh;
    const float* kb = g_k + bh;
    const float* vb = g_v + bh;

    // Load Q tile (transpose [d][na] -> [i][d])
#pragma unroll
    for (int i = 0; i < 4; i++) {
        int fidx = i * 128 + t;
        int d = fidx >> 4, j4 = (fidx & 15) * 4;
        float4 gq = *(const float4*)&qb[(d << 10) + i0 + j4];
        Qs[j4 + 0][d] = gq.x; Qs[j4 + 1][d] = gq.y;
        Qs[j4 + 2][d] = gq.z; Qs[j4 + 3][d] = gq.w;
    }

    float m_r[4], l_r[4], o_acc[4][4];
#pragma unroll
    for (int r = 0; r < 4; r++) {
        m_r[r] = -1e30f; l_r[r] = 0.f;
#pragma unroll
        for (int d = 0; d < 4; d++) o_acc[r][d] = 0.f;
    }

    for (int j0 = 0; j0 < NA; j0 += 64) {
        __syncthreads();
#pragma unroll
        for (int i = 0; i < 4; i++) {
            int fidx = i * 128 + t;
            int d = fidx >> 4, j4 = (fidx & 15) * 4;
            float4 gk = *(const float4*)&kb[(d << 10) + j0 + j4];
            Ks[j4 + 0][d] = gk.x; Ks[j4 + 1][d] = gk.y;
            Ks[j4 + 2][d] = gk.z; Ks[j4 + 3][d] = gk.w;
            float4 gv = *(const float4*)&vb[(d << 10) + j0 + j4];
            Vs[j4 + 0][d] = gv.x; Vs[j4 + 1][d] = gv.y;
            Vs[j4 + 2][d] = gv.z; Vs[j4 + 3][d] = gv.w;
        }
        __syncthreads();

        // S = Q K^T  (per thread 4 rows x 8 cols)
        float s[4][8];
#pragma unroll
        for (int r = 0; r < 4; r++)
#pragma unroll
            for (int j = 0; j < 8; j++) s[r][j] = 0.f;
#pragma unroll
        for (int kk = 0; kk < 32; kk += 4) {
            float4 kf[8];
#pragma unroll
            for (int j = 0; j < 8; j++) kf[j] = *(const float4*)&Ks[cc * 8 + j][kk];
#pragma unroll
            for (int r = 0; r < 4; r++) {
                float4 qf = *(const float4*)&Qs[rg * 4 + r][kk];
#pragma unroll
                for (int j = 0; j < 8; j++) {
                    s[r][j] += qf.x * kf[j].x;
                    s[r][j] += qf.y * kf[j].y;
                    s[r][j] += qf.z * kf[j].z;
                    s[r][j] += qf.w * kf[j].w;
                }
            }
        }

        // Online softmax update (row stats reduced over the 8 cc lanes)
#pragma unroll
        for (int r = 0; r < 4; r++) {
            float tmax = s[r][0];
#pragma unroll
            for (int j = 1; j < 8; j++) tmax = fmaxf(tmax, s[r][j]);
            tmax = fmaxf(tmax, __shfl_xor_sync(0xffffffffu, tmax, 1));
            tmax = fmaxf(tmax, __shfl_xor_sync(0xffffffffu, tmax, 2));
            tmax = fmaxf(tmax, __shfl_xor_sync(0xffffffffu, tmax, 4));
            float m_new = fmaxf(m_r[r], tmax);
            float alpha = __expf(m_r[r] - m_new);
            m_r[r] = m_new;
            float p[8];
            float rsum = 0.f;
#pragma unroll
            for (int j = 0; j < 8; j++) { p[j] = __expf(s[r][j] - m_new); rsum += p[j]; }
            rsum += __shfl_xor_sync(0xffffffffu, rsum, 1);
            rsum += __shfl_xor_sync(0xffffffffu, rsum, 2);
            rsum += __shfl_xor_sync(0xffffffffu, rsum, 4);
            l_r[r] = l_r[r] * alpha + rsum;
#pragma unroll
            for (int d = 0; d < 4; d++) o_acc[r][d] *= alpha;
            *(float4*)&Ps[rg * 4 + r][cc * 8] = make_float4(p[0], p[1], p[2], p[3]);
            *(float4*)&Ps[rg * 4 + r][cc * 8 + 4] = make_float4(p[4], p[5], p[6], p[7]);
        }
        __syncthreads();

        // O += P V  (per thread 4 rows x 4 d-cols)
#pragma unroll
        for (int j = 0; j < 64; j += 4) {
            float4 pv[4];
#pragma unroll
            for (int r = 0; r < 4; r++) pv[r] = *(const float4*)&Ps[rg * 4 + r][j];
            float vvf[4][4];
#pragma unroll
            for (int jj = 0; jj < 4; jj++) {
                float4 vv = *(const float4*)&Vs[j + jj][cc * 4];
                vvf[jj][0] = vv.x; vvf[jj][1] = vv.y; vvf[jj][2] = vv.z; vvf[jj][3] = vv.w;
            }
#pragma unroll
            for (int r = 0; r < 4; r++) {
                float pr[4] = {pv[r].x, pv[r].y, pv[r].z, pv[r].w};
#pragma unroll
                for (int jj = 0; jj < 4; jj++) {
                    o_acc[r][0] += pr[jj] * vvf[jj][0];
                    o_acc[r][1] += pr[jj] * vvf[jj][1];
                    o_acc[r][2] += pr[jj] * vvf[jj][2];
                    o_acc[r][3] += pr[jj] * vvf[jj][3];
                }
            }
        }
    }

    // Finalize: O /= l, transpose through smem, write coalesced to g_tmp[B,C,N]
    __syncthreads();
#pragma unroll
    for (int r = 0; r < 4; r++) {
        float inv = 1.f / l_r[r];
#pragma unroll
        for (int d = 0; d < 4; d++)
            Ps[cc * 4 + d][rg * 4 + r] = o_acc[r][d] * inv;  // O^T[d][i]
    }
    __syncthreads();
    {
        const int d = t >> 2, iq = (t & 3) * 16;
        float* op = g_tmp + (((size_t)(ba >> 2) * 256 + h * 32 + d) << 12)
                    + (ba & 3) * 1024 + i0 + iq;
#pragma unroll
        for (int j = 0; j < 16; j += 4)
            *(float4*)&op[j] = *(const float4*)&Ps[d][iq + j];
    }
}

// ---------------------------------------------------------------------------
// Kernel 3: g_tmp += dwconv7x7(g_vf) + b_pe. One block per (b,c) plane.
// grid 1024, block 256.
// ---------------------------------------------------------------------------
__global__ __launch_bounds__(256) void pe_kernel(const float* __restrict__ wpe,
                                                 const float* __restrict__ bpe) {
    __shared__ float sm[70][72];
    __shared__ float wsm[49];
    const int bc = blockIdx.x;
    const int c = bc & 255;
    const int t = threadIdx.x;
    const float* src = g_vf + (size_t)bc * 4096;
    if (t < 49) wsm[t] = wpe[c * 49 + t];
    for (int e = t; e < 70 * 70; e += 256) {
        int yy = e / 70, xx = e % 70;
        int y = yy - 3, x = xx - 3;
        float v = 0.f;
        if ((unsigned)y < 64u && (unsigned)x < 64u) v = src[y * 64 + x];
        sm[yy][xx] = v;
    }
    __syncthreads();
    const float bb = bpe[c];
    float* dst = g_tmp + (size_t)bc * 4096;
    for (int p = t; p < 4096; p += 256) {
        int y = p >> 6, x = p & 63;
        float acc = bb;
#pragma unroll
        for (int dy = 0; dy < 7; dy++)
#pragma unroll
            for (int dx = 0; dx < 7; dx++)
                acc += wsm[dy * 7 + dx] * sm[y + dy][x + dx];
        dst[p] += acc;
    }
}

// ---------------------------------------------------------------------------
// Kernel 4: out = W_proj @ g_tmp + b_proj. grid (4096/64, 256/64, B), block 256.
// ---------------------------------------------------------------------------
__global__ __launch_bounds__(256) void proj_gemm(const float* __restrict__ w,
                                                 const float* __restrict__ bias,
                                                 float* __restrict__ out) {
    __shared__ float Ws[16][64];
    __shared__ float Xs[16][64];
    const int nBase = blockIdx.x * 64;
    const int oBase = blockIdx.y * 64;
    const int b = blockIdx.z;
    const int t = threadIdx.x;
    const int tx = t & 15, ty = t >> 4;
    const float* xb = g_tmp + (size_t)b * CC * NN;
    float acc[4][4] = {};
    const int wo = t >> 2, wk = (t & 3) * 4;
    const int xk = t >> 4, xn = (t & 15) * 4;
    for (int c0 = 0; c0 < CC; c0 += 16) {
        float4 wv = *(const float4*)&w[(size_t)(oBase + wo) * CC + c0 + wk];
        Ws[wk + 0][wo] = wv.x; Ws[wk + 1][wo] = wv.y;
        Ws[wk + 2][wo] = wv.z; Ws[wk + 3][wo] = wv.w;
        *(float4*)&Xs[xk][xn] = *(const float4*)&xb[(size_t)(c0 + xk) * NN + nBase + xn];
        __syncthreads();
#pragma unroll
        for (int kk = 0; kk < 16; kk++) {
            float4 av = *(const float4*)&Ws[kk][ty * 4];
            float4 bv = *(const float4*)&Xs[kk][tx * 4];
            float a[4] = {av.x, av.y, av.z, av.w};
            float bb2[4] = {bv.x, bv.y, bv.z, bv.w};
#pragma unroll
            for (int i = 0; i < 4; i++)
#pragma unroll
                for (int j = 0; j < 4; j++)
                    acc[i][j] += a[i] * bb2[j];
        }
        __syncthreads();
    }
#pragma unroll
    for (int i = 0; i < 4; i++) {
        int o = oBase + ty * 4 + i;
        float bo = bias[o];
        float4 v4 = make_float4(acc[i][0] + bo, acc[i][1] + bo,
                                acc[i][2] + bo, acc[i][3] + bo);
        *(float4*)&out[(((size_t)b * 256 + o) << 12) + nBase + tx * 4] = v4;
    }
}

// ---------------------------------------------------------------------------
extern "C" void kernel_launch(void* const* d_in, const int* in_sizes, int n_in,
                              void* d_out, int out_size) {
    const float* x      = (const float*)d_in[0];
    const float* w_qkv  = (const float*)d_in[1];
    const float* b_qkv  = (const float*)d_in[2];
    const float* w_pe   = (const float*)d_in[3];
    const float* b_pe   = (const float*)d_in[4];
    const float* w_proj = (const float*)d_in[5];
    const float* b_proj = (const float*)d_in[6];
    float* out = (float*)d_out;

    qkv_gemm<<<dim3(64, 12, 4), 256>>>(x, w_qkv, b_qkv);
    attn_kernel<<<dim3(16, 8, 16), 128>>>();
    pe_kernel<<<1024, 256>>>(w_pe, b_pe);
    proj_gemm<<<dim3(64, 4, 4), 256>>>(w_proj, b_proj, out);
}

// round 2
// speedup vs baseline: 1.0016x; 1.0016x over previous
#include <cuda_runtime.h>

#define BB 4
#define CC 256
#define NN 4096
#define NH 8
#define HD 32
#define NA 1024

// Scratch (device globals — no allocations allowed)
__device__ float g_q[16 * 8 * 32 * 1024];   // [ba][h][d][na], pre-scaled by hd^-0.5
__device__ float g_k[16 * 8 * 32 * 1024];   // [ba][h][d][na]
__device__ float g_v[16 * 8 * 32 * 1024];   // [ba][h][d][na]
__device__ float g_vf[4 * 256 * 4096];      // [b][c][n]  (v in NCHW for dwconv)
__device__ float g_tmp[4 * 256 * 4096];     // [b][c][n]  attn out + pe conv

// ---------------------------------------------------------------------------
// Kernel 1: qkv = W_qkv @ x  (per batch: [768,256] x [256,4096]), scatter to
// q/k/v in [ba][h][hd][na] layout (+ v also to NCHW layout).
// grid (4096/64, 768/64, B), block 256.
// ---------------------------------------------------------------------------
__global__ __launch_bounds__(256) void qkv_gemm(const float* __restrict__ x,
                                                const float* __restrict__ w,
                                                const float* __restrict__ bias) {
    __shared__ float Ws[16][64];  // [k][o]
    __shared__ float Xs[16][64];  // [k][n]
    const int nBase = blockIdx.x * 64;
    const int oBase = blockIdx.y * 64;
    const int b = blockIdx.z;
    const int t = threadIdx.x;
    const int tx = t & 15, ty = t >> 4;
    const float* xb = x + (size_t)b * CC * NN;
    float acc[4][4] = {};
    const int wo = t >> 2, wk = (t & 3) * 4;
    const int xk = t >> 4, xn = (t & 15) * 4;
    for (int c0 = 0; c0 < CC; c0 += 16) {
        float4 wv = *(const float4*)&w[(size_t)(oBase + wo) * CC + c0 + wk];
        Ws[wk + 0][wo] = wv.x; Ws[wk + 1][wo] = wv.y;
        Ws[wk + 2][wo] = wv.z; Ws[wk + 3][wo] = wv.w;
        *(float4*)&Xs[xk][xn] = *(const float4*)&xb[(size_t)(c0 + xk) * NN + nBase + xn];
        __syncthreads();
#pragma unroll
        for (int kk = 0; kk < 16; kk++) {
            float4 av = *(const float4*)&Ws[kk][ty * 4];
            float4 bv = *(const float4*)&Xs[kk][tx * 4];
            float a[4] = {av.x, av.y, av.z, av.w};
            float bb2[4] = {bv.x, bv.y, bv.z, bv.w};
#pragma unroll
            for (int i = 0; i < 4; i++)
#pragma unroll
                for (int j = 0; j < 4; j++)
                    acc[i][j] += a[i] * bb2[j];
        }
        __syncthreads();
    }
    const int n0 = nBase + tx * 4;
    const int ba = b * 4 + (n0 >> 10);
    const int na = n0 & 1023;
#pragma unroll
    for (int i = 0; i < 4; i++) {
        int o = oBase + ty * 4 + i;
        int h = o / 96, rem = o % 96;
        int typ = rem >> 5, d = rem & 31;
        float bo = bias[o];
        float4 v4 = make_float4(acc[i][0] + bo, acc[i][1] + bo,
                                acc[i][2] + bo, acc[i][3] + bo);
        size_t idx = (((size_t)(ba * 8 + h) * 32 + d) << 10) + na;
        if (typ == 0) {
            const float s = 0.17677669529663687f;  // 32^-0.5
            v4.x *= s; v4.y *= s; v4.z *= s; v4.w *= s;
            *(float4*)&g_q[idx] = v4;
        } else if (typ == 1) {
            *(float4*)&g_k[idx] = v4;
        } else {
            *(float4*)&g_v[idx] = v4;
            *(float4*)&g_vf[(((size_t)b * 256 + h * 32 + d) << 12) + n0] = v4;
        }
    }
}

// ---------------------------------------------------------------------------
// Kernel 2: flash attention per (row-tile 64, head, ba). Block 128 threads.
// Online softmax; P staged through smem; output to g_tmp[B,C,N] coalesced.
// grid (1024/64, 8, 16).
// ---------------------------------------------------------------------------
__global__ __launch_bounds__(128) void attn_kernel() {
    __shared__ float Qs[64][36];  // [i][d]
    __shared__ float Ks[64][36];  // [j][d]
    __shared__ float Vs[64][36];  // [j][d]
    __shared__ float Ps[64][76];  // P tile; reused as O^T [32][64] at the end
    const int i0 = blockIdx.x * 64;
    const int h = blockIdx.y;
    const int ba = blockIdx.z;
    const int t = threadIdx.x;
    const int rg = t >> 3;   // row group: owns rows rg*4 .. rg*4+3
    const int cc = t & 7;    // col group: owns S cols cc*8.., O cols cc*4..
    const size_t bh = (size_t)(ba * 8 + h) * (32 * 1024);
    const float* qb = g_q + bh;
    const float* kb = g_k + bh;
    const float* vb = g_v + bh;

    // Load Q tile (transpose [d][na] -> [i][d])
#pragma unroll
    for (int i = 0; i < 4; i++) {
        int fidx = i * 128 + t;
        int d = fidx >> 4, j4 = (fidx & 15) * 4;
        float4 gq = *(const float4*)&qb[(d << 10) + i0 + j4];
        Qs[j4 + 0][d] = gq.x; Qs[j4 + 1][d] = gq.y;
        Qs[j4 + 2][d] = gq.z; Qs[j4 + 3][d] = gq.w;
    }

    float m_r[4], l_r[4], o_acc[4][4];
#pragma unroll
    for (int r = 0; r < 4; r++) {
        m_r[r] = -1e30f; l_r[r] = 0.f;
#pragma unroll
        for (int d = 0; d < 4; d++) o_acc[r][d] = 0.f;
    }

    for (int j0 = 0; j0 < NA; j0 += 64) {
        __syncthreads();
#pragma unroll
        for (int i = 0; i < 4; i++) {
            int fidx = i * 128 + t;
            int d = fidx >> 4, j4 = (fidx & 15) * 4;
            float4 gk = *(const float4*)&kb[(d << 10) + j0 + j4];
            Ks[j4 + 0][d] = gk.x; Ks[j4 + 1][d] = gk.y;
            Ks[j4 + 2][d] = gk.z; Ks[j4 + 3][d] = gk.w;
            float4 gv = *(const float4*)&vb[(d << 10) + j0 + j4];
            Vs[j4 + 0][d] = gv.x; Vs[j4 + 1][d] = gv.y;
            Vs[j4 + 2][d] = gv.z; Vs[j4 + 3][d] = gv.w;
        }
        __syncthreads();

        // S = Q K^T  (per thread 4 rows x 8 cols)
        float s[4][8];
#pragma unroll
        for (int r = 0; r < 4; r++)
#pragma unroll
            for (int j = 0; j < 8; j++) s[r][j] = 0.f;
#pragma unroll
        for (int kk = 0; kk < 32; kk += 4) {
            float4 kf[8];
#pragma unroll
            for (int j = 0; j < 8; j++) kf[j] = *(const float4*)&Ks[cc * 8 + j][kk];
#pragma unroll
            for (int r = 0; r < 4; r++) {
                float4 qf = *(const float4*)&Qs[rg * 4 + r][kk];
#pragma unroll
                for (int j = 0; j < 8; j++) {
                    s[r][j] += qf.x * kf[j].x;
                    s[r][j] += qf.y * kf[j].y;
                    s[r][j] += qf.z * kf[j].z;
                    s[r][j] += qf.w * kf[j].w;
                }
            }
        }

        // Online softmax update (row stats reduced over the 8 cc lanes)
#pragma unroll
        for (int r = 0; r < 4; r++) {
            float tmax = s[r][0];
#pragma unroll
            for (int j = 1; j < 8; j++) tmax = fmaxf(tmax, s[r][j]);
            tmax = fmaxf(tmax, __shfl_xor_sync(0xffffffffu, tmax, 1));
            tmax = fmaxf(tmax, __shfl_xor_sync(0xffffffffu, tmax, 2));
            tmax = fmaxf(tmax, __shfl_xor_sync(0xffffffffu, tmax, 4));
            float m_new = fmaxf(m_r[r], tmax);
            float alpha = __expf(m_r[r] - m_new);
            m_r[r] = m_new;
            float p[8];
            float rsum = 0.f;
#pragma unroll
            for (int j = 0; j < 8; j++) { p[j] = __expf(s[r][j] - m_new); rsum += p[j]; }
            rsum += __shfl_xor_sync(0xffffffffu, rsum, 1);
            rsum += __shfl_xor_sync(0xffffffffu, rsum, 2);
            rsum += __shfl_xor_sync(0xffffffffu, rsum, 4);
            l_r[r] = l_r[r] * alpha + rsum;
#pragma unroll
            for (int d = 0; d < 4; d++) o_acc[r][d] *= alpha;
            *(float4*)&Ps[rg * 4 + r][cc * 8] = make_float4(p[0], p[1], p[2], p[3]);
            *(float4*)&Ps[rg * 4 + r][cc * 8 + 4] = make_float4(p[4], p[5], p[6], p[7]);
        }
        __syncthreads();

        // O += P V  (per thread 4 rows x 4 d-cols)
#pragma unroll
        for (int j = 0; j < 64; j += 4) {
            float4 pv[4];
#pragma unroll
            for (int r = 0; r < 4; r++) pv[r] = *(const float4*)&Ps[rg * 4 + r][j];
            float vvf[4][4];
#pragma unroll
            for (int jj = 0; jj < 4; jj++) {
                float4 vv = *(const float4*)&Vs[j + jj][cc * 4];
                vvf[jj][0] = vv.x; vvf[jj][1] = vv.y; vvf[jj][2] = vv.z; vvf[jj][3] = vv.w;
            }
#pragma unroll
            for (int r = 0; r < 4; r++) {
                float pr[4] = {pv[r].x, pv[r].y, pv[r].z, pv[r].w};
#pragma unroll
                for (int jj = 0; jj < 4; jj++) {
                    o_acc[r][0] += pr[jj] * vvf[jj][0];
                    o_acc[r][1] += pr[jj] * vvf[jj][1];
                    o_acc[r][2] += pr[jj] * vvf[jj][2];
                    o_acc[r][3] += pr[jj] * vvf[jj][3];
                }
            }
        }
    }

    // Finalize: O /= l, transpose through smem, write coalesced to g_tmp[B,C,N]
    __syncthreads();
#pragma unroll
    for (int r = 0; r < 4; r++) {
        float inv = 1.f / l_r[r];
#pragma unroll
        for (int d = 0; d < 4; d++)
            Ps[cc * 4 + d][rg * 4 + r] = o_acc[r][d] * inv;  // O^T[d][i]
    }
    __syncthreads();
    {
        const int d = t >> 2, iq = (t & 3) * 16;
        float* op = g_tmp + (((size_t)(ba >> 2) * 256 + h * 32 + d) << 12)
                    + (ba & 3) * 1024 + i0 + iq;
#pragma unroll
        for (int j = 0; j < 16; j += 4)
            *(float4*)&op[j] = *(const float4*)&Ps[d][iq + j];
    }
}

// ---------------------------------------------------------------------------
// Kernel 3: g_tmp += dwconv7x7(g_vf) + b_pe. One block per (b,c) plane.
// grid 1024, block 256.
// ---------------------------------------------------------------------------
__global__ __launch_bounds__(256) void pe_kernel(const float* __restrict__ wpe,
                                                 const float* __restrict__ bpe) {
    __shared__ float sm[70][72];
    __shared__ float wsm[49];
    const int bc = blockIdx.x;
    const int c = bc & 255;
    const int t = threadIdx.x;
    const float* src = g_vf + (size_t)bc * 4096;
    if (t < 49) wsm[t] = wpe[c * 49 + t];
    for (int e = t; e < 70 * 70; e += 256) {
        int yy = e / 70, xx = e % 70;
        int y = yy - 3, x = xx - 3;
        float v = 0.f;
        if ((unsigned)y < 64u && (unsigned)x < 64u) v = src[y * 64 + x];
        sm[yy][xx] = v;
    }
    __syncthreads();
    const float bb = bpe[c];
    float* dst = g_tmp + (size_t)bc * 4096;
    for (int p = t; p < 4096; p += 256) {
        int y = p >> 6, x = p & 63;
        float acc = bb;
#pragma unroll
        for (int dy = 0; dy < 7; dy++)
#pragma unroll
            for (int dx = 0; dx < 7; dx++)
                acc += wsm[dy * 7 + dx] * sm[y + dy][x + dx];
        dst[p] += acc;
    }
}

// ---------------------------------------------------------------------------
// Kernel 4: out = W_proj @ g_tmp + b_proj. grid (4096/64, 256/64, B), block 256.
// ---------------------------------------------------------------------------
__global__ __launch_bounds__(256) void proj_gemm(const float* __restrict__ w,
                                                 const float* __restrict__ bias,
                                                 float* __restrict__ out) {
    __shared__ float Ws[16][64];
    __shared__ float Xs[16][64];
    const int nBase = blockIdx.x * 64;
    const int oBase = blockIdx.y * 64;
    const int b = blockIdx.z;
    const int t = threadIdx.x;
    const int tx = t & 15, ty = t >> 4;
    const float* xb = g_tmp + (size_t)b * CC * NN;
    float acc[4][4] = {};
    const int wo = t >> 2, wk = (t & 3) * 4;
    const int xk = t >> 4, xn = (t & 15) * 4;
    for (int c0 = 0; c0 < CC; c0 += 16) {
        float4 wv = *(const float4*)&w[(size_t)(oBase + wo) * CC + c0 + wk];
        Ws[wk + 0][wo] = wv.x; Ws[wk + 1][wo] = wv.y;
        Ws[wk + 2][wo] = wv.z; Ws[wk + 3][wo] = wv.w;
        *(float4*)&Xs[xk][xn] = *(const float4*)&xb[(size_t)(c0 + xk) * NN + nBase + xn];
        __syncthreads();
#pragma unroll
        for (int kk = 0; kk < 16; kk++) {
            float4 av = *(const float4*)&Ws[kk][ty * 4];
            float4 bv = *(const float4*)&Xs[kk][tx * 4];
            float a[4] = {av.x, av.y, av.z, av.w};
            float bb2[4] = {bv.x, bv.y, bv.z, bv.w};
#pragma unroll
            for (int i = 0; i < 4; i++)
#pragma unroll
                for (int j = 0; j < 4; j++)
                    acc[i][j] += a[i] * bb2[j];
        }
        __syncthreads();
    }
#pragma unroll
    for (int i = 0; i < 4; i++) {
        int o = oBase + ty * 4 + i;
        float bo = bias[o];
        float4 v4 = make_float4(acc[i][0] + bo, acc[i][1] + bo,
                                acc[i][2] + bo, acc[i][3] + bo);
        *(float4*)&out[(((size_t)b * 256 + o) << 12) + nBase + tx * 4] = v4;
    }
}

// ---------------------------------------------------------------------------
extern "C" void kernel_launch(void* const* d_in, const int* in_sizes, int n_in,
                              void* d_out, int out_size) {
    const float* x      = (const float*)d_in[0];
    const float* w_qkv  = (const float*)d_in[1];
    const float* b_qkv  = (const float*)d_in[2];
    const float* w_pe   = (const float*)d_in[3];
    const float* b_pe   = (const float*)d_in[4];
    const float* w_proj = (const float*)d_in[5];
    const float* b_proj = (const float*)d_in[6];
    float* out = (float*)d_out;

    qkv_gemm<<<dim3(64, 12, 4), 256>>>(x, w_qkv, b_qkv);
    attn_kernel<<<dim3(16, 8, 16), 128>>>();
    pe_kernel<<<1024, 256>>>(w_pe, b_pe);
    proj_gemm<<<dim3(64, 4, 4), 256>>>(w_proj, b_proj, out);
}

// round 4
// speedup vs baseline: 3.5259x; 3.5203x over previous
#include <cuda_runtime.h>
#include <cuda_bf16.h>
#include <cstdint>

#define CC 256
#define NN 4096
#define NA 1024

// Scratch (device globals)
__device__ float g_q[128 * 32 * 1024];            // [bh][d][na], scaled hd^-0.5
__device__ float g_k[128 * 32 * 1024];            // [bh][d][na]
__device__ float g_v[128 * 32 * 1024];            // [bh][d][na]
__device__ __nv_bfloat16 g_kh[128 * 1024 * 32];   // [bh][na][d] hi plane
__device__ __nv_bfloat16 g_kl[128 * 1024 * 32];   // [bh][na][d] lo plane
__device__ __nv_bfloat16 g_vp[128 * 32 * 1024];   // [bh][d][na] bf16
__device__ float g_vf[4 * 256 * 4096];            // [b][c][n] (v NCHW)
__device__ float g_tmp[4 * 256 * 4096];           // [b][c][n]

// ---------------- helpers ----------------
__device__ __forceinline__ uint32_t smem_to_u32(const void* p) {
    uint32_t a;
    asm("{ .reg .u64 t; cvta.to.shared.u64 t, %1; cvt.u32.u64 %0, t; }" : "=r"(a) : "l"(p));
    return a;
}
__device__ __forceinline__ void ldsm4(uint32_t r[4], uint32_t addr) {
    asm volatile("ldmatrix.sync.aligned.m8n8.x4.shared.b16 {%0,%1,%2,%3}, [%4];"
                 : "=r"(r[0]), "=r"(r[1]), "=r"(r[2]), "=r"(r[3]) : "r"(addr));
}
__device__ __forceinline__ void mma16816(float c[4], const uint32_t a[4], const uint32_t b[2]) {
    asm volatile("mma.sync.aligned.m16n8k16.row.col.f32.bf16.bf16.f32 "
                 "{%0,%1,%2,%3}, {%4,%5,%6,%7}, {%8,%9}, {%0,%1,%2,%3};"
                 : "+f"(c[0]), "+f"(c[1]), "+f"(c[2]), "+f"(c[3])
                 : "r"(a[0]), "r"(a[1]), "r"(a[2]), "r"(a[3]), "r"(b[0]), "r"(b[1]));
}
__device__ __forceinline__ uint2 split2(float a, float b) {
    __nv_bfloat162 h = __floats2bfloat162_rn(a, b);
    __nv_bfloat162 l = __floats2bfloat162_rn(a - __bfloat162float(h.x), b - __bfloat162float(h.y));
    return make_uint2(*(uint32_t*)&h, *(uint32_t*)&l);
}

// ---------------------------------------------------------------------------
// Kernel 1: qkv = W_qkv @ x, scatter to q/k/v [bh][d][na] (+ v NCHW).
// ---------------------------------------------------------------------------
__global__ __launch_bounds__(256) void qkv_gemm(const float* __restrict__ x,
                                                const float* __restrict__ w,
                                                const float* __restrict__ bias) {
    __shared__ float Ws[16][64];
    __shared__ float Xs[16][64];
    const int nBase = blockIdx.x * 64, oBase = blockIdx.y * 64, b = blockIdx.z;
    const int t = threadIdx.x, tx = t & 15, ty = t >> 4;
    const float* xb = x + (size_t)b * CC * NN;
    float acc[4][4] = {};
    const int wo = t >> 2, wk = (t & 3) * 4;
    const int xk = t >> 4, xn = (t & 15) * 4;
    for (int c0 = 0; c0 < CC; c0 += 16) {
        float4 wv = *(const float4*)&w[(size_t)(oBase + wo) * CC + c0 + wk];
        Ws[wk + 0][wo] = wv.x; Ws[wk + 1][wo] = wv.y;
        Ws[wk + 2][wo] = wv.z; Ws[wk + 3][wo] = wv.w;
        *(float4*)&Xs[xk][xn] = *(const float4*)&xb[(size_t)(c0 + xk) * NN + nBase + xn];
        __syncthreads();
#pragma unroll
        for (int kk = 0; kk < 16; kk++) {
            float4 av = *(const float4*)&Ws[kk][ty * 4];
            float4 bv = *(const float4*)&Xs[kk][tx * 4];
            float a[4] = {av.x, av.y, av.z, av.w};
            float bb2[4] = {bv.x, bv.y, bv.z, bv.w};
#pragma unroll
            for (int i = 0; i < 4; i++)
#pragma unroll
                for (int j = 0; j < 4; j++) acc[i][j] += a[i] * bb2[j];
        }
        __syncthreads();
    }
    const int n0 = nBase + tx * 4;
    const int ba = b * 4 + (n0 >> 10);
    const int na = n0 & 1023;
#pragma unroll
    for (int i = 0; i < 4; i++) {
        int o = oBase + ty * 4 + i;
        int h = o / 96, rem = o % 96, typ = (rem >> 5), d = rem & 31;
        float bo = bias[o];
        float4 v4 = make_float4(acc[i][0] + bo, acc[i][1] + bo, acc[i][2] + bo, acc[i][3] + bo);
        size_t idx = (((size_t)(ba * 8 + h) * 32 + d) << 10) + na;
        if (typ == 0) {
            const float s = 0.17677669529663687f;
            v4.x *= s; v4.y *= s; v4.z *= s; v4.w *= s;
            *(float4*)&g_q[idx] = v4;
        } else if (typ == 1) {
            *(float4*)&g_k[idx] = v4;
        } else {
            *(float4*)&g_v[idx] = v4;
            *(float4*)&g_vf[(((size_t)b * 256 + h * 32 + d) << 12) + n0] = v4;
        }
    }
}

// ---------------------------------------------------------------------------
// Kernel 1b: repack — K transpose+split to [na][d] hi/lo bf16, V -> bf16 [d][na].
// grid (8, 128), 256 threads.
// ---------------------------------------------------------------------------
__global__ __launch_bounds__(256) void repack() {
    __shared__ float ts[32][132];
    const int bh = blockIdx.y, na0 = blockIdx.x * 128, t = threadIdx.x;
    const float* ksrc = g_k + (size_t)bh * 32768;
#pragma unroll
    for (int i = 0; i < 4; i++) {
        int idx = i * 256 + t, row = idx >> 5, c4 = (idx & 31) * 4;
        *(float4*)&ts[row][c4] = *(const float4*)&ksrc[row * 1024 + na0 + c4];
    }
    __syncthreads();
    {
        int j = t >> 1, half = t & 1;
        uint32_t wh[8], wl[8];
#pragma unroll
        for (int m = 0; m < 8; m++) {
            uint2 s = split2(ts[half * 16 + 2 * m][j], ts[half * 16 + 2 * m + 1][j]);
            wh[m] = s.x; wl[m] = s.y;
        }
        size_t off = ((size_t)bh * 1024 + na0 + j) * 32 + half * 16;
        *(uint4*)&g_kh[off]     = make_uint4(wh[0], wh[1], wh[2], wh[3]);
        *(uint4*)&g_kh[off + 8] = make_uint4(wh[4], wh[5], wh[6], wh[7]);
        *(uint4*)&g_kl[off]     = make_uint4(wl[0], wl[1], wl[2], wl[3]);
        *(uint4*)&g_kl[off + 8] = make_uint4(wl[4], wl[5], wl[6], wl[7]);
    }
    // V: elementwise fp32 -> bf16, [d][na]
    const float* vsrc = g_v + (size_t)bh * 32768;
    __nv_bfloat16* vdst = g_vp + (size_t)bh * 32768;
#pragma unroll
    for (int i = 0; i < 4; i++) {
        int idx = i * 256 + t, d = idx >> 5, c4 = (idx & 31) * 4;
        float4 v = *(const float4*)&vsrc[d * 1024 + na0 + c4];
        __nv_bfloat162 a = __floats2bfloat162_rn(v.x, v.y);
        __nv_bfloat162 b = __floats2bfloat162_rn(v.z, v.w);
        *(uint2*)&vdst[d * 1024 + na0 + c4] = make_uint2(*(uint32_t*)&a, *(uint32_t*)&b);
    }
}

// ---------------------------------------------------------------------------
// Kernel 2: HMMA flash attention. grid (8 i-tiles, 128 bh), 256 threads.
// smem: Q stage [128][72] bf16 (18432 B), then KH[64][40] / KL[64][40] /
//       V[32][72] at offsets 0 / 5120 / 10240.
// ---------------------------------------------------------------------------
#define SM_KH 0
#define SM_KL 5120
#define SM_V  10240

__global__ __launch_bounds__(256, 2) void attn3() {
    __shared__ __align__(128) uint8_t shm[18432];
    const int t = threadIdx.x;
    const int wid = t >> 5, lane = t & 31;
    const int i0 = blockIdx.x * 128, bh = blockIdx.y;
    const uint32_t sb = smem_to_u32(shm);

    // ---- stage Q hi/lo: rows = i (0..127), 72 bf16/row: hi d0-31, lo at +32
    {
        const float* qp = g_q + (size_t)bh * 32768 + i0;
        __nv_bfloat16* qs = (__nv_bfloat16*)shm;
#pragma unroll
        for (int e = 0; e < 16; e++) {
            int idx = e * 256 + t;
            int d = idx >> 7, i = idx & 127;
            float v = qp[d * 1024 + i];
            __nv_bfloat16 h = __float2bfloat16(v);
            __nv_bfloat16 l = __float2bfloat16(v - __bfloat162float(h));
            qs[i * 72 + d] = h;
            qs[i * 72 + 32 + d] = l;
        }
    }
    __syncthreads();

    // ---- Q A-fragments: [plane][kstep][4]
    uint32_t aq[2][2][4];
    {
        int grp = lane >> 3;
        int row = wid * 16 + (grp & 1) * 8 + (lane & 7);
        uint32_t base = sb + row * 144 + ((grp >> 1) & 1) * 16;
        ldsm4(aq[0][0], base + 0);
        ldsm4(aq[0][1], base + 32);
        ldsm4(aq[1][0], base + 64);
        ldsm4(aq[1][1], base + 96);
    }
    __syncthreads();

    float o[4][4];
#pragma unroll
    for (int dt = 0; dt < 4; dt++)
#pragma unroll
        for (int j = 0; j < 4; j++) o[dt][j] = 0.f;
    float m0 = -1e30f, m1 = -1e30f, l0 = 0.f, l1 = 0.f;

    const __nv_bfloat16* khp = g_kh + (size_t)bh * 32768;
    const __nv_bfloat16* klp = g_kl + (size_t)bh * 32768;
    const __nv_bfloat16* vp  = g_vp + (size_t)bh * 32768;

    for (int jt = 0; jt < 16; jt++) {
        const int j0 = jt * 64;
        // ---- stage K hi/lo [64][40] and V [32][72]
        {
            int r = t >> 2, c = t & 3;  // 64 rows x 4 16B-chunks
            *(uint4*)(shm + SM_KH + r * 80 + c * 16) =
                *(const uint4*)(khp + (size_t)(j0 + r) * 32 + c * 8);
            *(uint4*)(shm + SM_KL + r * 80 + c * 16) =
                *(const uint4*)(klp + (size_t)(j0 + r) * 32 + c * 8);
            int vr = t >> 3, vc = t & 7;  // 32 rows x 8 chunks
            *(uint4*)(shm + SM_V + vr * 144 + vc * 16) =
                *(const uint4*)(vp + (size_t)vr * 1024 + j0 + vc * 8);
        }
        __syncthreads();

        // ---- S = Qh*Kh + Qh*Kl + Ql*Kh   (M=16/warp, N=64, K=32)
        float cfr[8][4];
#pragma unroll
        for (int nt = 0; nt < 8; nt++) {
            cfr[nt][0] = cfr[nt][1] = cfr[nt][2] = cfr[nt][3] = 0.f;
            uint32_t bhf[4], blf[4];
            uint32_t ka = sb + SM_KH + (nt * 8 + (lane & 7)) * 80 + (lane >> 3) * 16;
            ldsm4(bhf, ka);
            ldsm4(blf, ka + (SM_KL - SM_KH));
            mma16816(cfr[nt], aq[0][0], bhf + 0);
            mma16816(cfr[nt], aq[0][1], bhf + 2);
            mma16816(cfr[nt], aq[0][0], blf + 0);
            mma16816(cfr[nt], aq[0][1], blf + 2);
            mma16816(cfr[nt], aq[1][0], bhf + 0);
            mma16816(cfr[nt], aq[1][1], bhf + 2);
        }

        // ---- online softmax (rows r0 = lane>>2, r1 = r0+8; quad shares row)
        float mx0 = -1e30f, mx1 = -1e30f;
#pragma unroll
        for (int nt = 0; nt < 8; nt++) {
            mx0 = fmaxf(mx0, fmaxf(cfr[nt][0], cfr[nt][1]));
            mx1 = fmaxf(mx1, fmaxf(cfr[nt][2], cfr[nt][3]));
        }
        mx0 = fmaxf(mx0, __shfl_xor_sync(0xffffffffu, mx0, 1));
        mx0 = fmaxf(mx0, __shfl_xor_sync(0xffffffffu, mx0, 2));
        mx1 = fmaxf(mx1, __shfl_xor_sync(0xffffffffu, mx1, 1));
        mx1 = fmaxf(mx1, __shfl_xor_sync(0xffffffffu, mx1, 2));
        float mn0 = fmaxf(m0, mx0), mn1 = fmaxf(m1, mx1);
        float al0 = __expf(m0 - mn0), al1 = __expf(m1 - mn1);
        m0 = mn0; m1 = mn1;

        uint32_t pah[4][4], pal[4][4];
        float sum0 = 0.f, sum1 = 0.f;
#pragma unroll
        for (int nt = 0; nt < 8; nt++) {
            float p0 = __expf(cfr[nt][0] - mn0);
            float p1 = __expf(cfr[nt][1] - mn0);
            float p2 = __expf(cfr[nt][2] - mn1);
            float p3 = __expf(cfr[nt][3] - mn1);
            sum0 += p0 + p1; sum1 += p2 + p3;
            uint2 s01 = split2(p0, p1);
            uint2 s23 = split2(p2, p3);
            int ks = nt >> 1, sl = (nt & 1) * 2;
            pah[ks][sl] = s01.x; pah[ks][sl + 1] = s23.x;
            pal[ks][sl] = s01.y; pal[ks][sl + 1] = s23.y;
        }
        sum0 += __shfl_xor_sync(0xffffffffu, sum0, 1);
        sum0 += __shfl_xor_sync(0xffffffffu, sum0, 2);
        sum1 += __shfl_xor_sync(0xffffffffu, sum1, 1);
        sum1 += __shfl_xor_sync(0xffffffffu, sum1, 2);
        l0 = l0 * al0 + sum0;
        l1 = l1 * al1 + sum1;

        // ---- rescale O, then O += (Ph + Pl) * V
#pragma unroll
        for (int dt = 0; dt < 4; dt++) {
            o[dt][0] *= al0; o[dt][1] *= al0;
            o[dt][2] *= al1; o[dt][3] *= al1;
        }
#pragma unroll
        for (int dt = 0; dt < 4; dt++) {
#pragma unroll
            for (int jh = 0; jh < 2; jh++) {
                uint32_t bv[4];
                ldsm4(bv, sb + SM_V + (dt * 8 + (lane & 7)) * 144 + jh * 64 + (lane >> 3) * 16);
                int ks = jh * 2;
                mma16816(o[dt], pah[ks], bv + 0);
                mma16816(o[dt], pah[ks + 1], bv + 2);
                mma16816(o[dt], pal[ks], bv + 0);
                mma16816(o[dt], pal[ks + 1], bv + 2);
            }
        }
        __syncthreads();
    }

    // ---- epilogue: normalize, write g_tmp[b][c][n]
    const float inv0 = 1.f / l0, inv1 = 1.f / l1;
    const int b = bh >> 5, h = bh & 7, a3 = (bh >> 3) & 3;
    float* outb = g_tmp + (((size_t)(b * 256 + h * 32)) << 12) + (a3 << 10) + i0;
    const int r0 = wid * 16 + (lane >> 2), r1 = r0 + 8;
#pragma unroll
    for (int dt = 0; dt < 4; dt++) {
        int d = dt * 8 + (lane & 3) * 2;
        outb[((size_t)d << 12) + r0]       = o[dt][0] * inv0;
        outb[((size_t)(d + 1) << 12) + r0] = o[dt][1] * inv0;
        outb[((size_t)d << 12) + r1]       = o[dt][2] * inv1;
        outb[((size_t)(d + 1) << 12) + r1] = o[dt][3] * inv1;
    }
}

// ---------------------------------------------------------------------------
// Kernel 3: g_tmp += dwconv7x7(g_vf) + b_pe
// ---------------------------------------------------------------------------
__global__ __launch_bounds__(256) void pe_kernel(const float* __restrict__ wpe,
                                                 const float* __restrict__ bpe) {
    __shared__ float smp[70][72];
    __shared__ float wsm[49];
    const int bc = blockIdx.x, c = bc & 255, t = threadIdx.x;
    const float* src = g_vf + (size_t)bc * 4096;
    if (t < 49) wsm[t] = wpe[c * 49 + t];
    for (int e = t; e < 70 * 70; e += 256) {
        int yy = e / 70, xx = e % 70, y = yy - 3, x = xx - 3;
        float v = 0.f;
        if ((unsigned)y < 64u && (unsigned)x < 64u) v = src[y * 64 + x];
        smp[yy][xx] = v;
    }
    __syncthreads();
    const float bb = bpe[c];
    float* dst = g_tmp + (size_t)bc * 4096;
    for (int p = t; p < 4096; p += 256) {
        int y = p >> 6, x = p & 63;
        float acc = bb;
#pragma unroll
        for (int dy = 0; dy < 7; dy++)
#pragma unroll
            for (int dx = 0; dx < 7; dx++) acc += wsm[dy * 7 + dx] * smp[y + dy][x + dx];
        dst[p] += acc;
    }
}

// ---------------------------------------------------------------------------
// Kernel 4: out = W_proj @ g_tmp + b_proj
// ---------------------------------------------------------------------------
__global__ __launch_bounds__(256) void proj_gemm(const float* __restrict__ w,
                                                 const float* __restrict__ bias,
                                                 float* __restrict__ out) {
    __shared__ float Ws[16][64];
    __shared__ float Xs[16][64];
    const int nBase = blockIdx.x * 64, oBase = blockIdx.y * 64, b = blockIdx.z;
    const int t = threadIdx.x, tx = t & 15, ty = t >> 4;
    const float* xb = g_tmp + (size_t)b * CC * NN;
    float acc[4][4] = {};
    const int wo = t >> 2, wk = (t & 3) * 4;
    const int xk = t >> 4, xn = (t & 15) * 4;
    for (int c0 = 0; c0 < CC; c0 += 16) {
        float4 wv = *(const float4*)&w[(size_t)(oBase + wo) * CC + c0 + wk];
        Ws[wk + 0][wo] = wv.x; Ws[wk + 1][wo] = wv.y;
        Ws[wk + 2][wo] = wv.z; Ws[wk + 3][wo] = wv.w;
        *(float4*)&Xs[xk][xn] = *(const float4*)&xb[(size_t)(c0 + xk) * NN + nBase + xn];
        __syncthreads();
#pragma unroll
        for (int kk = 0; kk < 16; kk++) {
            float4 av = *(const float4*)&Ws[kk][ty * 4];
            float4 bv = *(const float4*)&Xs[kk][tx * 4];
            float a[4] = {av.x, av.y, av.z, av.w};
            float bb2[4] = {bv.x, bv.y, bv.z, bv.w};
#pragma unroll
            for (int i = 0; i < 4; i++)
#pragma unroll
                for (int j = 0; j < 4; j++) acc[i][j] += a[i] * bb2[j];
        }
        __syncthreads();
    }
#pragma unroll
    for (int i = 0; i < 4; i++) {
        int o = oBase + ty * 4 + i;
        float bo = bias[o];
        float4 v4 = make_float4(acc[i][0] + bo, acc[i][1] + bo, acc[i][2] + bo, acc[i][3] + bo);
        *(float4*)&out[(((size_t)b * 256 + o) << 12) + nBase + tx * 4] = v4;
    }
}

// ---------------------------------------------------------------------------
extern "C" void kernel_launch(void* const* d_in, const int* in_sizes, int n_in,
                              void* d_out, int out_size) {
    const float* x      = (const float*)d_in[0];
    const float* w_qkv  = (const float*)d_in[1];
    const float* b_qkv  = (const float*)d_in[2];
    const float* w_pe   = (const float*)d_in[3];
    const float* b_pe   = (const float*)d_in[4];
    const float* w_proj = (const float*)d_in[5];
    const float* b_proj = (const float*)d_in[6];
    float* out = (float*)d_out;

    qkv_gemm<<<dim3(64, 12, 4), 256>>>(x, w_qkv, b_qkv);
    repack<<<dim3(8, 128), 256>>>();
    attn3<<<dim3(8, 128), 256>>>();
    pe_kernel<<<1024, 256>>>(w_pe, b_pe);
    proj_gemm<<<dim3(64, 4, 4), 256>>>(w_proj, b_proj, out);
}

// round 5
// speedup vs baseline: 5.2428x; 1.4869x over previous
#include <cuda_runtime.h>
#include <cuda_bf16.h>
#include <cstdint>

#define CC 256
#define NN 4096
#define NA 1024

// Scratch (device globals)
__device__ float g_q[128 * 32 * 1024];            // [bh][d][na], scaled hd^-0.5
__device__ float g_k[128 * 32 * 1024];            // [bh][d][na]
__device__ float g_v[128 * 32 * 1024];            // [bh][d][na]
__device__ __nv_bfloat16 g_kh[128 * 1024 * 32];   // [bh][na][d] hi plane
__device__ __nv_bfloat16 g_kl[128 * 1024 * 32];   // [bh][na][d] lo plane
__device__ __nv_bfloat16 g_vp[128 * 32 * 1024];   // [bh][d][na] bf16
__device__ float g_vf[4 * 256 * 4096];            // [b][c][n] (v NCHW)
__device__ float g_tmp[4 * 256 * 4096];           // [b][c][n]

// ---------------- helpers ----------------
__device__ __forceinline__ uint32_t smem_to_u32(const void* p) {
    uint32_t a;
    asm("{ .reg .u64 t; cvta.to.shared.u64 t, %1; cvt.u32.u64 %0, t; }" : "=r"(a) : "l"(p));
    return a;
}
__device__ __forceinline__ void ldsm4(uint32_t r[4], uint32_t addr) {
    asm volatile("ldmatrix.sync.aligned.m8n8.x4.shared.b16 {%0,%1,%2,%3}, [%4];"
                 : "=r"(r[0]), "=r"(r[1]), "=r"(r[2]), "=r"(r[3]) : "r"(addr));
}
__device__ __forceinline__ void ldsm4t(uint32_t r[4], uint32_t addr) {
    asm volatile("ldmatrix.sync.aligned.m8n8.x4.trans.shared.b16 {%0,%1,%2,%3}, [%4];"
                 : "=r"(r[0]), "=r"(r[1]), "=r"(r[2]), "=r"(r[3]) : "r"(addr));
}
__device__ __forceinline__ void mma16816(float c[4], const uint32_t a[4], const uint32_t b[2]) {
    asm volatile("mma.sync.aligned.m16n8k16.row.col.f32.bf16.bf16.f32 "
                 "{%0,%1,%2,%3}, {%4,%5,%6,%7}, {%8,%9}, {%0,%1,%2,%3};"
                 : "+f"(c[0]), "+f"(c[1]), "+f"(c[2]), "+f"(c[3])
                 : "r"(a[0]), "r"(a[1]), "r"(a[2]), "r"(a[3]), "r"(b[0]), "r"(b[1]));
}
__device__ __forceinline__ uint2 split2(float a, float b) {
    __nv_bfloat162 h = __floats2bfloat162_rn(a, b);
    __nv_bfloat162 l = __floats2bfloat162_rn(a - __bfloat162float(h.x), b - __bfloat162float(h.y));
    return make_uint2(*(uint32_t*)&h, *(uint32_t*)&l);
}

// ---------------------------------------------------------------------------
// Shared GEMM body: C[128o x 128n] = W[128,256] @ X[256,128n], split-bf16 HMMA.
// smem planes: WH 0 [128][40], WL 10240, XH 20480 [32][136], XL 29184.
// 8 warps: warp (wm=wid>>1) rows 32, (wn=wid&1) cols 64.
// ---------------------------------------------------------------------------
__device__ __forceinline__ void gemm_body(float c[2][8][4], uint8_t* shm,
                                          const float* __restrict__ xb,
                                          const float* __restrict__ w) {
    const int t = threadIdx.x, lane = t & 31, wid = t >> 5;
    const int wm = wid >> 1, wn = wid & 1;
    const int nBase = blockIdx.x * 128, oBase = blockIdx.y * 128;
    const uint32_t sb = smem_to_u32(shm);
    const int grp = lane >> 3;

    for (int kc = 0; kc < 8; kc++) {
        const int k0 = kc * 32;
        if (kc) __syncthreads();
        // stage W tile [128 o][32 k] -> hi/lo
#pragma unroll
        for (int e = 0; e < 4; e++) {
            int idx = e * 256 + t;
            int row = idx >> 3, c4 = (idx & 7) * 4;
            float4 v = *(const float4*)&w[(size_t)(oBase + row) * 256 + k0 + c4];
            uint2 s0 = split2(v.x, v.y);
            uint2 s1 = split2(v.z, v.w);
            *(uint2*)(shm + 0 + row * 80 + c4 * 2) = make_uint2(s0.x, s1.x);
            *(uint2*)(shm + 10240 + row * 80 + c4 * 2) = make_uint2(s0.y, s1.y);
        }
        // stage X tile [32 k][128 n] -> hi/lo
#pragma unroll
        for (int e = 0; e < 4; e++) {
            int idx = e * 256 + t;
            int row = idx >> 5, c4 = (idx & 31) * 4;
            float4 v = *(const float4*)&xb[(size_t)(k0 + row) * 4096 + nBase + c4];
            uint2 s0 = split2(v.x, v.y);
            uint2 s1 = split2(v.z, v.w);
            *(uint2*)(shm + 20480 + row * 272 + c4 * 2) = make_uint2(s0.x, s1.x);
            *(uint2*)(shm + 29184 + row * 272 + c4 * 2) = make_uint2(s0.y, s1.y);
        }
        __syncthreads();

        // A fragments [kk][mi]
        uint32_t ah[2][2][4], al[2][2][4];
#pragma unroll
        for (int kk = 0; kk < 2; kk++)
#pragma unroll
            for (int mi = 0; mi < 2; mi++) {
                uint32_t arow = wm * 32 + mi * 16 + (grp & 1) * 8 + (lane & 7);
                uint32_t ab = arow * 80 + kk * 32 + ((grp >> 1) & 1) * 16;
                ldsm4(ah[kk][mi], sb + ab);
                ldsm4(al[kk][mi], sb + 10240 + ab);
            }
#pragma unroll
        for (int ni = 0; ni < 8; ni++) {
            uint32_t bh4[4], bl4[4];
            uint32_t bb = lane * 272 + (wn * 64 + ni * 8) * 2;
            ldsm4t(bh4, sb + 20480 + bb);
            ldsm4t(bl4, sb + 29184 + bb);
#pragma unroll
            for (int kk = 0; kk < 2; kk++)
#pragma unroll
                for (int mi = 0; mi < 2; mi++) {
                    mma16816(c[mi][ni], ah[kk][mi], bh4 + kk * 2);
                    mma16816(c[mi][ni], ah[kk][mi], bl4 + kk * 2);
                    mma16816(c[mi][ni], al[kk][mi], bh4 + kk * 2);
                }
        }
    }
}

// ---------------------------------------------------------------------------
// Kernel 1: qkv via HMMA, scatter epilogue. grid (32, 6, 4), 256 threads.
// ---------------------------------------------------------------------------
__global__ __launch_bounds__(256, 2) void qkv_hmma(const float* __restrict__ x,
                                                   const float* __restrict__ w,
                                                   const float* __restrict__ bias) {
    __shared__ __align__(128) uint8_t shm[37888];
    float c[2][8][4] = {};
    const int b = blockIdx.z;
    gemm_body(c, shm, x + (size_t)b * (256 * 4096), w);

    const int t = threadIdx.x, lane = t & 31, wid = t >> 5;
    const int wm = wid >> 1, wn = wid & 1;
    const int nBase = blockIdx.x * 128, oBase = blockIdx.y * 128;
    const int ncol0 = nBase + wn * 64 + (lane & 3) * 2;
#pragma unroll
    for (int mi = 0; mi < 2; mi++)
#pragma unroll
        for (int half = 0; half < 2; half++) {
            int o = oBase + wm * 32 + mi * 16 + half * 8 + (lane >> 2);
            int h = o / 96, rem = o % 96, typ = rem >> 5, d = rem & 31;
            float bo = bias[o];
#pragma unroll
            for (int ni = 0; ni < 8; ni++) {
                int n = ncol0 + ni * 8;
                float v0 = c[mi][ni][half * 2 + 0] + bo;
                float v1 = c[mi][ni][half * 2 + 1] + bo;
                int ba = b * 4 + (n >> 10), na = n & 1023;
                size_t idx = (((size_t)(ba * 8 + h) * 32 + d) << 10) + na;
                if (typ == 0) {
                    const float s = 0.17677669529663687f;
                    *(float2*)&g_q[idx] = make_float2(v0 * s, v1 * s);
                } else if (typ == 1) {
                    *(float2*)&g_k[idx] = make_float2(v0, v1);
                } else {
                    *(float2*)&g_v[idx] = make_float2(v0, v1);
                    *(float2*)&g_vf[(((size_t)(b * 256 + h * 32 + d)) << 12) + n] =
                        make_float2(v0, v1);
                }
            }
        }
}

// ---------------------------------------------------------------------------
// Kernel 1b: repack — K transpose+split to [na][d] hi/lo bf16, V -> bf16 [d][na].
// ---------------------------------------------------------------------------
__global__ __launch_bounds__(256) void repack() {
    __shared__ float ts[32][132];
    const int bh = blockIdx.y, na0 = blockIdx.x * 128, t = threadIdx.x;
    const float* ksrc = g_k + (size_t)bh * 32768;
#pragma unroll
    for (int i = 0; i < 4; i++) {
        int idx = i * 256 + t, row = idx >> 5, c4 = (idx & 31) * 4;
        *(float4*)&ts[row][c4] = *(const float4*)&ksrc[row * 1024 + na0 + c4];
    }
    __syncthreads();
    {
        int j = t >> 1, half = t & 1;
        uint32_t wh[8], wl[8];
#pragma unroll
        for (int m = 0; m < 8; m++) {
            uint2 s = split2(ts[half * 16 + 2 * m][j], ts[half * 16 + 2 * m + 1][j]);
            wh[m] = s.x; wl[m] = s.y;
        }
        size_t off = ((size_t)bh * 1024 + na0 + j) * 32 + half * 16;
        *(uint4*)&g_kh[off]     = make_uint4(wh[0], wh[1], wh[2], wh[3]);
        *(uint4*)&g_kh[off + 8] = make_uint4(wh[4], wh[5], wh[6], wh[7]);
        *(uint4*)&g_kl[off]     = make_uint4(wl[0], wl[1], wl[2], wl[3]);
        *(uint4*)&g_kl[off + 8] = make_uint4(wl[4], wl[5], wl[6], wl[7]);
    }
    const float* vsrc = g_v + (size_t)bh * 32768;
    __nv_bfloat16* vdst = g_vp + (size_t)bh * 32768;
#pragma unroll
    for (int i = 0; i < 4; i++) {
        int idx = i * 256 + t, d = idx >> 5, c4 = (idx & 31) * 4;
        float4 v = *(const float4*)&vsrc[d * 1024 + na0 + c4];
        __nv_bfloat162 a = __floats2bfloat162_rn(v.x, v.y);
        __nv_bfloat162 b = __floats2bfloat162_rn(v.z, v.w);
        *(uint2*)&vdst[d * 1024 + na0 + c4] = make_uint2(*(uint32_t*)&a, *(uint32_t*)&b);
    }
}

// ---------------------------------------------------------------------------
// Kernel 2: HMMA flash attention (unchanged from R4 pass).
// ---------------------------------------------------------------------------
#define SM_KH 0
#define SM_KL 5120
#define SM_V  10240

__global__ __launch_bounds__(256, 2) void attn3() {
    __shared__ __align__(128) uint8_t shm[18432];
    const int t = threadIdx.x;
    const int wid = t >> 5, lane = t & 31;
    const int i0 = blockIdx.x * 128, bh = blockIdx.y;
    const uint32_t sb = smem_to_u32(shm);

    {
        const float* qp = g_q + (size_t)bh * 32768 + i0;
        __nv_bfloat16* qs = (__nv_bfloat16*)shm;
#pragma unroll
        for (int e = 0; e < 16; e++) {
            int idx = e * 256 + t;
            int d = idx >> 7, i = idx & 127;
            float v = qp[d * 1024 + i];
            __nv_bfloat16 h = __float2bfloat16(v);
            __nv_bfloat16 l = __float2bfloat16(v - __bfloat162float(h));
            qs[i * 72 + d] = h;
            qs[i * 72 + 32 + d] = l;
        }
    }
    __syncthreads();

    uint32_t aq[2][2][4];
    {
        int grp = lane >> 3;
        int row = wid * 16 + (grp & 1) * 8 + (lane & 7);
        uint32_t base = sb + row * 144 + ((grp >> 1) & 1) * 16;
        ldsm4(aq[0][0], base + 0);
        ldsm4(aq[0][1], base + 32);
        ldsm4(aq[1][0], base + 64);
        ldsm4(aq[1][1], base + 96);
    }
    __syncthreads();

    float o[4][4];
#pragma unroll
    for (int dt = 0; dt < 4; dt++)
#pragma unroll
        for (int j = 0; j < 4; j++) o[dt][j] = 0.f;
    float m0 = -1e30f, m1 = -1e30f, l0 = 0.f, l1 = 0.f;

    const __nv_bfloat16* khp = g_kh + (size_t)bh * 32768;
    const __nv_bfloat16* klp = g_kl + (size_t)bh * 32768;
    const __nv_bfloat16* vp  = g_vp + (size_t)bh * 32768;

    for (int jt = 0; jt < 16; jt++) {
        const int j0 = jt * 64;
        {
            int r = t >> 2, cjs = t & 3;
            *(uint4*)(shm + SM_KH + r * 80 + cjs * 16) =
                *(const uint4*)(khp + (size_t)(j0 + r) * 32 + cjs * 8);
            *(uint4*)(shm + SM_KL + r * 80 + cjs * 16) =
                *(const uint4*)(klp + (size_t)(j0 + r) * 32 + cjs * 8);
            int vr = t >> 3, vc = t & 7;
            *(uint4*)(shm + SM_V + vr * 144 + vc * 16) =
                *(const uint4*)(vp + (size_t)vr * 1024 + j0 + vc * 8);
        }
        __syncthreads();

        float cfr[8][4];
#pragma unroll
        for (int nt = 0; nt < 8; nt++) {
            cfr[nt][0] = cfr[nt][1] = cfr[nt][2] = cfr[nt][3] = 0.f;
            uint32_t bhf[4], blf[4];
            uint32_t ka = sb + SM_KH + (nt * 8 + (lane & 7)) * 80 + (lane >> 3) * 16;
            ldsm4(bhf, ka);
            ldsm4(blf, ka + (SM_KL - SM_KH));
            mma16816(cfr[nt], aq[0][0], bhf + 0);
            mma16816(cfr[nt], aq[0][1], bhf + 2);
            mma16816(cfr[nt], aq[0][0], blf + 0);
            mma16816(cfr[nt], aq[0][1], blf + 2);
            mma16816(cfr[nt], aq[1][0], bhf + 0);
            mma16816(cfr[nt], aq[1][1], bhf + 2);
        }

        float mx0 = -1e30f, mx1 = -1e30f;
#pragma unroll
        for (int nt = 0; nt < 8; nt++) {
            mx0 = fmaxf(mx0, fmaxf(cfr[nt][0], cfr[nt][1]));
            mx1 = fmaxf(mx1, fmaxf(cfr[nt][2], cfr[nt][3]));
        }
        mx0 = fmaxf(mx0, __shfl_xor_sync(0xffffffffu, mx0, 1));
        mx0 = fmaxf(mx0, __shfl_xor_sync(0xffffffffu, mx0, 2));
        mx1 = fmaxf(mx1, __shfl_xor_sync(0xffffffffu, mx1, 1));
        mx1 = fmaxf(mx1, __shfl_xor_sync(0xffffffffu, mx1, 2));
        float mn0 = fmaxf(m0, mx0), mn1 = fmaxf(m1, mx1);
        float al0 = __expf(m0 - mn0), al1 = __expf(m1 - mn1);
        m0 = mn0; m1 = mn1;

        uint32_t pah[4][4], pal[4][4];
        float sum0 = 0.f, sum1 = 0.f;
#pragma unroll
        for (int nt = 0; nt < 8; nt++) {
            float p0 = __expf(cfr[nt][0] - mn0);
            float p1 = __expf(cfr[nt][1] - mn0);
            float p2 = __expf(cfr[nt][2] - mn1);
            float p3 = __expf(cfr[nt][3] - mn1);
            sum0 += p0 + p1; sum1 += p2 + p3;
            uint2 s01 = split2(p0, p1);
            uint2 s23 = split2(p2, p3);
            int ks = nt >> 1, sl = (nt & 1) * 2;
            pah[ks][sl] = s01.x; pah[ks][sl + 1] = s23.x;
            pal[ks][sl] = s01.y; pal[ks][sl + 1] = s23.y;
        }
        sum0 += __shfl_xor_sync(0xffffffffu, sum0, 1);
        sum0 += __shfl_xor_sync(0xffffffffu, sum0, 2);
        sum1 += __shfl_xor_sync(0xffffffffu, sum1, 1);
        sum1 += __shfl_xor_sync(0xffffffffu, sum1, 2);
        l0 = l0 * al0 + sum0;
        l1 = l1 * al1 + sum1;

#pragma unroll
        for (int dt = 0; dt < 4; dt++) {
            o[dt][0] *= al0; o[dt][1] *= al0;
            o[dt][2] *= al1; o[dt][3] *= al1;
        }
#pragma unroll
        for (int dt = 0; dt < 4; dt++) {
#pragma unroll
            for (int jh = 0; jh < 2; jh++) {
                uint32_t bv[4];
                ldsm4(bv, sb + SM_V + (dt * 8 + (lane & 7)) * 144 + jh * 64 + (lane >> 3) * 16);
                int ks = jh * 2;
                mma16816(o[dt], pah[ks], bv + 0);
                mma16816(o[dt], pah[ks + 1], bv + 2);
                mma16816(o[dt], pal[ks], bv + 0);
                mma16816(o[dt], pal[ks + 1], bv + 2);
            }
        }
        __syncthreads();
    }

    const float inv0 = 1.f / l0, inv1 = 1.f / l1;
    const int b = bh >> 5, h = bh & 7, a3 = (bh >> 3) & 3;
    float* outb = g_tmp + (((size_t)(b * 256 + h * 32)) << 12) + (a3 << 10) + i0;
    const int r0 = wid * 16 + (lane >> 2), r1 = r0 + 8;
#pragma unroll
    for (int dt = 0; dt < 4; dt++) {
        int d = dt * 8 + (lane & 3) * 2;
        outb[((size_t)d << 12) + r0]       = o[dt][0] * inv0;
        outb[((size_t)(d + 1) << 12) + r0] = o[dt][1] * inv0;
        outb[((size_t)d << 12) + r1]       = o[dt][2] * inv1;
        outb[((size_t)(d + 1) << 12) + r1] = o[dt][3] * inv1;
    }
}

// ---------------------------------------------------------------------------
// Kernel 3: g_tmp += dwconv7x7(g_vf) + b_pe. Register-window version.
// ---------------------------------------------------------------------------
__global__ __launch_bounds__(256) void pe_kernel(const float* __restrict__ wpe,
                                                 const float* __restrict__ bpe) {
    __shared__ float smp[70][72];
    __shared__ float wsm[49];
    const int bc = blockIdx.x, c = bc & 255, t = threadIdx.x;
    const float* src = g_vf + (size_t)bc * 4096;
    if (t < 49) wsm[t] = wpe[c * 49 + t];
    for (int e = t; e < 70 * 70; e += 256) {
        int yy = e / 70, xx = e % 70, y = yy - 3, x = xx - 3;
        float v = 0.f;
        if ((unsigned)y < 64u && (unsigned)x < 64u) v = src[y * 64 + x];
        smp[yy][xx] = v;
    }
    __syncthreads();
    const float bb = bpe[c];
    float* dst = g_tmp + (size_t)bc * 4096;
    const int txx = t & 7, tyy = t >> 3;
#pragma unroll
    for (int pass = 0; pass < 2; pass++) {
        const int y = tyy + pass * 32;
        const int x0 = txx * 8;
        float acc[8];
#pragma unroll
        for (int j = 0; j < 8; j++) acc[j] = bb;
#pragma unroll
        for (int dy = 0; dy < 7; dy++) {
            float win[16];
            *(float4*)&win[0]  = *(const float4*)&smp[y + dy][x0 + 0];
            *(float4*)&win[4]  = *(const float4*)&smp[y + dy][x0 + 4];
            *(float4*)&win[8]  = *(const float4*)&smp[y + dy][x0 + 8];
            *(float4*)&win[12] = *(const float4*)&smp[y + dy][x0 + 12];
#pragma unroll
            for (int dx = 0; dx < 7; dx++) {
                float wv = wsm[dy * 7 + dx];
#pragma unroll
                for (int j = 0; j < 8; j++) acc[j] += wv * win[j + dx];
            }
        }
        float4 d0 = *(float4*)&dst[y * 64 + x0];
        float4 d1 = *(float4*)&dst[y * 64 + x0 + 4];
        d0.x += acc[0]; d0.y += acc[1]; d0.z += acc[2]; d0.w += acc[3];
        d1.x += acc[4]; d1.y += acc[5]; d1.z += acc[6]; d1.w += acc[7];
        *(float4*)&dst[y * 64 + x0] = d0;
        *(float4*)&dst[y * 64 + x0 + 4] = d1;
    }
}

// ---------------------------------------------------------------------------
// Kernel 4: proj via HMMA. grid (32, 2, 4), 256 threads.
// ---------------------------------------------------------------------------
__global__ __launch_bounds__(256, 2) void proj_hmma(const float* __restrict__ w,
                                                    const float* __restrict__ bias,
                                                    float* __restrict__ out) {
    __shared__ __align__(128) uint8_t shm[37888];
    float c[2][8][4] = {};
    const int b = blockIdx.z;
    gemm_body(c, shm, g_tmp + (size_t)b * (256 * 4096), w);

    const int t = threadIdx.x, lane = t & 31, wid = t >> 5;
    const int wm = wid >> 1, wn = wid & 1;
    const int nBase = blockIdx.x * 128, oBase = blockIdx.y * 128;
    const int ncol0 = nBase + wn * 64 + (lane & 3) * 2;
#pragma unroll
    for (int mi = 0; mi < 2; mi++)
#pragma unroll
        for (int half = 0; half < 2; half++) {
            int o = oBase + wm * 32 + mi * 16 + half * 8 + (lane >> 2);
            float bo = bias[o];
            float* orow = out + (((size_t)(b * 256 + o)) << 12);
#pragma unroll
            for (int ni = 0; ni < 8; ni++) {
                int n = ncol0 + ni * 8;
                *(float2*)&orow[n] = make_float2(c[mi][ni][half * 2 + 0] + bo,
                                                 c[mi][ni][half * 2 + 1] + bo);
            }
        }
}

// ---------------------------------------------------------------------------
extern "C" void kernel_launch(void* const* d_in, const int* in_sizes, int n_in,
                              void* d_out, int out_size) {
    const float* x      = (const float*)d_in[0];
    const float* w_qkv  = (const float*)d_in[1];
    const float* b_qkv  = (const float*)d_in[2];
    const float* w_pe   = (const float*)d_in[3];
    const float* b_pe   = (const float*)d_in[4];
    const float* w_proj = (const float*)d_in[5];
    const float* b_proj = (const float*)d_in[6];
    float* out = (float*)d_out;

    qkv_hmma<<<dim3(32, 6, 4), 256>>>(x, w_qkv, b_qkv);
    repack<<<dim3(8, 128), 256>>>();
    attn3<<<dim3(8, 128), 256>>>();
    pe_kernel<<<1024, 256>>>(w_pe, b_pe);
    proj_hmma<<<dim3(32, 2, 4), 256>>>(w_proj, b_proj, out);
}

// round 6
// speedup vs baseline: 5.4415x; 1.0379x over previous
#include <cuda_runtime.h>
#include <cuda_bf16.h>
#include <cstdint>

#define CC 256
#define NN 4096
#define NA 1024

// Scratch (device globals)
__device__ float g_q[128 * 32 * 1024];            // [bh][d][na], scaled hd^-0.5
__device__ float g_k[128 * 32 * 1024];            // [bh][d][na]
__device__ __nv_bfloat16 g_kh[128 * 1024 * 32];   // [bh][na][d] hi plane
__device__ __nv_bfloat16 g_kl[128 * 1024 * 32];   // [bh][na][d] lo plane
__device__ __nv_bfloat16 g_vp[128 * 32 * 1024];   // [bh][d][na] bf16
__device__ float g_vf[4 * 256 * 4096];            // [b][c][n] (v NCHW)
__device__ float g_tmp[4 * 256 * 4096];           // [b][c][n] attn out
__device__ __nv_bfloat16 g_xh[4 * 256 * 4096];    // x hi plane
__device__ __nv_bfloat16 g_xl[4 * 256 * 4096];    // x lo plane
__device__ __nv_bfloat16 g_th[4 * 256 * 4096];    // (attn+pe) hi plane
__device__ __nv_bfloat16 g_tl[4 * 256 * 4096];    // (attn+pe) lo plane
__device__ __nv_bfloat16 g_wqh[768 * 256], g_wql[768 * 256];
__device__ __nv_bfloat16 g_wph[256 * 256], g_wpl[256 * 256];

// ---------------- helpers ----------------
__device__ __forceinline__ uint32_t smem_to_u32(const void* p) {
    uint32_t a;
    asm("{ .reg .u64 t; cvta.to.shared.u64 t, %1; cvt.u32.u64 %0, t; }" : "=r"(a) : "l"(p));
    return a;
}
__device__ __forceinline__ void cp16(uint32_t saddr, const void* g) {
    asm volatile("cp.async.cg.shared.global [%0], [%1], 16;" :: "r"(saddr), "l"(g) : "memory");
}
__device__ __forceinline__ void ldsm4(uint32_t r[4], uint32_t addr) {
    asm volatile("ldmatrix.sync.aligned.m8n8.x4.shared.b16 {%0,%1,%2,%3}, [%4];"
                 : "=r"(r[0]), "=r"(r[1]), "=r"(r[2]), "=r"(r[3]) : "r"(addr));
}
__device__ __forceinline__ void ldsm4t(uint32_t r[4], uint32_t addr) {
    asm volatile("ldmatrix.sync.aligned.m8n8.x4.trans.shared.b16 {%0,%1,%2,%3}, [%4];"
                 : "=r"(r[0]), "=r"(r[1]), "=r"(r[2]), "=r"(r[3]) : "r"(addr));
}
__device__ __forceinline__ void mma16816(float c[4], const uint32_t a[4], const uint32_t b[2]) {
    asm volatile("mma.sync.aligned.m16n8k16.row.col.f32.bf16.bf16.f32 "
                 "{%0,%1,%2,%3}, {%4,%5,%6,%7}, {%8,%9}, {%0,%1,%2,%3};"
                 : "+f"(c[0]), "+f"(c[1]), "+f"(c[2]), "+f"(c[3])
                 : "r"(a[0]), "r"(a[1]), "r"(a[2]), "r"(a[3]), "r"(b[0]), "r"(b[1]));
}
__device__ __forceinline__ uint2 split2(float a, float b) {
    __nv_bfloat162 h = __floats2bfloat162_rn(a, b);
    __nv_bfloat162 l = __floats2bfloat162_rn(a - __bfloat162float(h.x), b - __bfloat162float(h.y));
    return make_uint2(*(uint32_t*)&h, *(uint32_t*)&l);
}

// ---------------------------------------------------------------------------
// Kernel 0a: split x -> bf16 hi/lo planes. grid 4096, 256 threads (float4 each)
// ---------------------------------------------------------------------------
__global__ __launch_bounds__(256) void split_x(const float* __restrict__ x) {
    size_t off = ((size_t)blockIdx.x * 256 + threadIdx.x) * 4;
    float4 v = *(const float4*)&x[off];
    uint2 s0 = split2(v.x, v.y);
    uint2 s1 = split2(v.z, v.w);
    *(uint2*)&g_xh[off] = make_uint2(s0.x, s1.x);
    *(uint2*)&g_xl[off] = make_uint2(s0.y, s1.y);
}

// ---------------------------------------------------------------------------
// Kernel 0b: split w_qkv + w_proj. grid 256, 256 threads.
// ---------------------------------------------------------------------------
__global__ __launch_bounds__(256) void split_w(const float* __restrict__ wq,
                                               const float* __restrict__ wp) {
    int id = blockIdx.x * 256 + threadIdx.x;  // 0..65535 float4s
    const float* src;
    __nv_bfloat16 *dh, *dl;
    size_t off;
    if (id < 49152) { src = wq; dh = g_wqh; dl = g_wql; off = (size_t)id * 4; }
    else            { src = wp; dh = g_wph; dl = g_wpl; off = (size_t)(id - 49152) * 4; }
    float4 v = *(const float4*)&src[off];
    uint2 s0 = split2(v.x, v.y);
    uint2 s1 = split2(v.z, v.w);
    *(uint2*)&dh[off] = make_uint2(s0.x, s1.x);
    *(uint2*)&dl[off] = make_uint2(s0.y, s1.y);
}

// ---------------------------------------------------------------------------
// GEMM core: C[128o x 128n] = W[128,256] @ X[256,128n], bf16 hi/lo inputs,
// cp.async 2-stage double buffer. Per buffer: WH 0 [128][40B], WL 10240,
// XH 20480 [32][272B], XL 29184; buffer stride 37888.
// ---------------------------------------------------------------------------
#define GBUF 37888
#define GSMEM (2 * GBUF)

__device__ __forceinline__ void gemm_core(float c[2][8][4], uint8_t* shm,
                                          const __nv_bfloat16* __restrict__ xh,
                                          const __nv_bfloat16* __restrict__ xl,
                                          const __nv_bfloat16* __restrict__ wh,
                                          const __nv_bfloat16* __restrict__ wl) {
    const int t = threadIdx.x, lane = t & 31, wid = t >> 5;
    const int wm = wid >> 1, wn = wid & 1;
    const int nBase = blockIdx.x * 128, oBase = blockIdx.y * 128;
    const uint32_t sb = smem_to_u32(shm);
    const int grp = lane >> 3;

    auto stage = [&](int buf, int kc) {
        const int k0 = kc * 32;
        uint32_t base = sb + buf * GBUF;
#pragma unroll
        for (int e = 0; e < 2; e++) {
            int cid = e * 256 + t;
            int row = cid >> 2, col = cid & 3;
            cp16(base + row * 80 + col * 16, wh + (size_t)(oBase + row) * 256 + k0 + col * 8);
            cp16(base + 10240 + row * 80 + col * 16, wl + (size_t)(oBase + row) * 256 + k0 + col * 8);
        }
#pragma unroll
        for (int e = 0; e < 2; e++) {
            int cid = e * 256 + t;
            int row = cid >> 4, col = cid & 15;
            cp16(base + 20480 + row * 272 + col * 16, xh + (size_t)(k0 + row) * 4096 + nBase + col * 8);
            cp16(base + 29184 + row * 272 + col * 16, xl + (size_t)(k0 + row) * 4096 + nBase + col * 8);
        }
        asm volatile("cp.async.commit_group;" ::: "memory");
    };

    stage(0, 0);
    for (int kc = 0; kc < 8; kc++) {
        if (kc < 7) {
            stage((kc + 1) & 1, kc + 1);
            asm volatile("cp.async.wait_group 1;" ::: "memory");
        } else {
            asm volatile("cp.async.wait_group 0;" ::: "memory");
        }
        __syncthreads();
        const uint32_t base = sb + (kc & 1) * GBUF;

        uint32_t ah[2][2][4], al[2][2][4];
#pragma unroll
        for (int kk = 0; kk < 2; kk++)
#pragma unroll
            for (int mi = 0; mi < 2; mi++) {
                uint32_t arow = wm * 32 + mi * 16 + (grp & 1) * 8 + (lane & 7);
                uint32_t ab = arow * 80 + kk * 32 + ((grp >> 1) & 1) * 16;
                ldsm4(ah[kk][mi], base + ab);
                ldsm4(al[kk][mi], base + 10240 + ab);
            }
#pragma unroll
        for (int ni = 0; ni < 8; ni++) {
            uint32_t bh4[4], bl4[4];
            uint32_t bb = lane * 272 + (wn * 64 + ni * 8) * 2;
            ldsm4t(bh4, base + 20480 + bb);
            ldsm4t(bl4, base + 29184 + bb);
#pragma unroll
            for (int kk = 0; kk < 2; kk++)
#pragma unroll
                for (int mi = 0; mi < 2; mi++) {
                    mma16816(c[mi][ni], ah[kk][mi], bh4 + kk * 2);
                    mma16816(c[mi][ni], ah[kk][mi], bl4 + kk * 2);
                    mma16816(c[mi][ni], al[kk][mi], bh4 + kk * 2);
                }
        }
        __syncthreads();
    }
}

// ---------------------------------------------------------------------------
// Kernel 1: qkv via HMMA, scatter epilogue (writes g_q, g_k, g_vp, g_vf).
// grid (32, 6, 4), 256 threads, dynamic smem GSMEM.
// ---------------------------------------------------------------------------
__global__ __launch_bounds__(256, 2) void qkv_hmma(const float* __restrict__ bias) {
    extern __shared__ __align__(128) uint8_t shm[];
    float c[2][8][4] = {};
    const int b = blockIdx.z;
    gemm_core(c, shm, g_xh + (size_t)b * (256 * 4096), g_xl + (size_t)b * (256 * 4096),
              g_wqh, g_wql);

    const int t = threadIdx.x, lane = t & 31, wid = t >> 5;
    const int wm = wid >> 1, wn = wid & 1;
    const int nBase = blockIdx.x * 128, oBase = blockIdx.y * 128;
    const int ncol0 = nBase + wn * 64 + (lane & 3) * 2;
#pragma unroll
    for (int mi = 0; mi < 2; mi++)
#pragma unroll
        for (int half = 0; half < 2; half++) {
            int o = oBase + wm * 32 + mi * 16 + half * 8 + (lane >> 2);
            int h = o / 96, rem = o % 96, typ = rem >> 5, d = rem & 31;
            float bo = bias[o];
#pragma unroll
            for (int ni = 0; ni < 8; ni++) {
                int n = ncol0 + ni * 8;
                float v0 = c[mi][ni][half * 2 + 0] + bo;
                float v1 = c[mi][ni][half * 2 + 1] + bo;
                int ba = b * 4 + (n >> 10), na = n & 1023;
                size_t idx = (((size_t)(ba * 8 + h) * 32 + d) << 10) + na;
                if (typ == 0) {
                    const float s = 0.17677669529663687f;
                    *(float2*)&g_q[idx] = make_float2(v0 * s, v1 * s);
                } else if (typ == 1) {
                    *(float2*)&g_k[idx] = make_float2(v0, v1);
                } else {
                    __nv_bfloat162 p = __floats2bfloat162_rn(v0, v1);
                    *(uint32_t*)&g_vp[idx] = *(uint32_t*)&p;
                    *(float2*)&g_vf[(((size_t)(b * 256 + h * 32 + d)) << 12) + n] =
                        make_float2(v0, v1);
                }
            }
        }
}

// ---------------------------------------------------------------------------
// Kernel 1b: repack — K transpose+split to [na][d] hi/lo bf16. grid (8,128).
// ---------------------------------------------------------------------------
__global__ __launch_bounds__(256) void repack() {
    __shared__ float ts[32][132];
    const int bh = blockIdx.y, na0 = blockIdx.x * 128, t = threadIdx.x;
    const float* ksrc = g_k + (size_t)bh * 32768;
#pragma unroll
    for (int i = 0; i < 4; i++) {
        int idx = i * 256 + t, row = idx >> 5, c4 = (idx & 31) * 4;
        *(float4*)&ts[row][c4] = *(const float4*)&ksrc[row * 1024 + na0 + c4];
    }
    __syncthreads();
    {
        int j = t >> 1, half = t & 1;
        uint32_t wh[8], wl[8];
#pragma unroll
        for (int m = 0; m < 8; m++) {
            uint2 s = split2(ts[half * 16 + 2 * m][j], ts[half * 16 + 2 * m + 1][j]);
            wh[m] = s.x; wl[m] = s.y;
        }
        size_t off = ((size_t)bh * 1024 + na0 + j) * 32 + half * 16;
        *(uint4*)&g_kh[off]     = make_uint4(wh[0], wh[1], wh[2], wh[3]);
        *(uint4*)&g_kh[off + 8] = make_uint4(wh[4], wh[5], wh[6], wh[7]);
        *(uint4*)&g_kl[off]     = make_uint4(wl[0], wl[1], wl[2], wl[3]);
        *(uint4*)&g_kl[off + 8] = make_uint4(wl[4], wl[5], wl[6], wl[7]);
    }
}

// ---------------------------------------------------------------------------
// Kernel 2: HMMA flash attention (unchanged from R5 pass).
// ---------------------------------------------------------------------------
#define SM_KH 0
#define SM_KL 5120
#define SM_V  10240

__global__ __launch_bounds__(256, 2) void attn3() {
    __shared__ __align__(128) uint8_t shma[18432];
    const int t = threadIdx.x;
    const int wid = t >> 5, lane = t & 31;
    const int i0 = blockIdx.x * 128, bh = blockIdx.y;
    const uint32_t sb = smem_to_u32(shma);

    {
        const float* qp = g_q + (size_t)bh * 32768 + i0;
        __nv_bfloat16* qs = (__nv_bfloat16*)shma;
#pragma unroll
        for (int e = 0; e < 16; e++) {
            int idx = e * 256 + t;
            int d = idx >> 7, i = idx & 127;
            float v = qp[d * 1024 + i];
            __nv_bfloat16 h = __float2bfloat16(v);
            __nv_bfloat16 l = __float2bfloat16(v - __bfloat162float(h));
            qs[i * 72 + d] = h;
            qs[i * 72 + 32 + d] = l;
        }
    }
    __syncthreads();

    uint32_t aq[2][2][4];
    {
        int grp = lane >> 3;
        int row = wid * 16 + (grp & 1) * 8 + (lane & 7);
        uint32_t base = sb + row * 144 + ((grp >> 1) & 1) * 16;
        ldsm4(aq[0][0], base + 0);
        ldsm4(aq[0][1], base + 32);
        ldsm4(aq[1][0], base + 64);
        ldsm4(aq[1][1], base + 96);
    }
    __syncthreads();

    float o[4][4];
#pragma unroll
    for (int dt = 0; dt < 4; dt++)
#pragma unroll
        for (int j = 0; j < 4; j++) o[dt][j] = 0.f;
    float m0 = -1e30f, m1 = -1e30f, l0 = 0.f, l1 = 0.f;

    const __nv_bfloat16* khp = g_kh + (size_t)bh * 32768;
    const __nv_bfloat16* klp = g_kl + (size_t)bh * 32768;
    const __nv_bfloat16* vp  = g_vp + (size_t)bh * 32768;

    for (int jt = 0; jt < 16; jt++) {
        const int j0 = jt * 64;
        {
            int r = t >> 2, cjs = t & 3;
            *(uint4*)(shma + SM_KH + r * 80 + cjs * 16) =
                *(const uint4*)(khp + (size_t)(j0 + r) * 32 + cjs * 8);
            *(uint4*)(shma + SM_KL + r * 80 + cjs * 16) =
                *(const uint4*)(klp + (size_t)(j0 + r) * 32 + cjs * 8);
            int vr = t >> 3, vc = t & 7;
            *(uint4*)(shma + SM_V + vr * 144 + vc * 16) =
                *(const uint4*)(vp + (size_t)vr * 1024 + j0 + vc * 8);
        }
        __syncthreads();

        float cfr[8][4];
#pragma unroll
        for (int nt = 0; nt < 8; nt++) {
            cfr[nt][0] = cfr[nt][1] = cfr[nt][2] = cfr[nt][3] = 0.f;
            uint32_t bhf[4], blf[4];
            uint32_t ka = sb + SM_KH + (nt * 8 + (lane & 7)) * 80 + (lane >> 3) * 16;
            ldsm4(bhf, ka);
            ldsm4(blf, ka + (SM_KL - SM_KH));
            mma16816(cfr[nt], aq[0][0], bhf + 0);
            mma16816(cfr[nt], aq[0][1], bhf + 2);
            mma16816(cfr[nt], aq[0][0], blf + 0);
            mma16816(cfr[nt], aq[0][1], blf + 2);
            mma16816(cfr[nt], aq[1][0], bhf + 0);
            mma16816(cfr[nt], aq[1][1], bhf + 2);
        }

        float mx0 = -1e30f, mx1 = -1e30f;
#pragma unroll
        for (int nt = 0; nt < 8; nt++) {
            mx0 = fmaxf(mx0, fmaxf(cfr[nt][0], cfr[nt][1]));
            mx1 = fmaxf(mx1, fmaxf(cfr[nt][2], cfr[nt][3]));
        }
        mx0 = fmaxf(mx0, __shfl_xor_sync(0xffffffffu, mx0, 1));
        mx0 = fmaxf(mx0, __shfl_xor_sync(0xffffffffu, mx0, 2));
        mx1 = fmaxf(mx1, __shfl_xor_sync(0xffffffffu, mx1, 1));
        mx1 = fmaxf(mx1, __shfl_xor_sync(0xffffffffu, mx1, 2));
        float mn0 = fmaxf(m0, mx0), mn1 = fmaxf(m1, mx1);
        float al0 = __expf(m0 - mn0), al1 = __expf(m1 - mn1);
        m0 = mn0; m1 = mn1;

        uint32_t pah[4][4], pal[4][4];
        float sum0 = 0.f, sum1 = 0.f;
#pragma unroll
        for (int nt = 0; nt < 8; nt++) {
            float p0 = __expf(cfr[nt][0] - mn0);
            float p1 = __expf(cfr[nt][1] - mn0);
            float p2 = __expf(cfr[nt][2] - mn1);
            float p3 = __expf(cfr[nt][3] - mn1);
            sum0 += p0 + p1; sum1 += p2 + p3;
            uint2 s01 = split2(p0, p1);
            uint2 s23 = split2(p2, p3);
            int ks = nt >> 1, sl = (nt & 1) * 2;
            pah[ks][sl] = s01.x; pah[ks][sl + 1] = s23.x;
            pal[ks][sl] = s01.y; pal[ks][sl + 1] = s23.y;
        }
        sum0 += __shfl_xor_sync(0xffffffffu, sum0, 1);
        sum0 += __shfl_xor_sync(0xffffffffu, sum0, 2);
        sum1 += __shfl_xor_sync(0xffffffffu, sum1, 1);
        sum1 += __shfl_xor_sync(0xffffffffu, sum1, 2);
        l0 = l0 * al0 + sum0;
        l1 = l1 * al1 + sum1;

#pragma unroll
        for (int dt = 0; dt < 4; dt++) {
            o[dt][0] *= al0; o[dt][1] *= al0;
            o[dt][2] *= al1; o[dt][3] *= al1;
        }
#pragma unroll
        for (int dt = 0; dt < 4; dt++) {
#pragma unroll
            for (int jh = 0; jh < 2; jh++) {
                uint32_t bv[4];
                ldsm4(bv, sb + SM_V + (dt * 8 + (lane & 7)) * 144 + jh * 64 + (lane >> 3) * 16);
                int ks = jh * 2;
                mma16816(o[dt], pah[ks], bv + 0);
                mma16816(o[dt], pah[ks + 1], bv + 2);
                mma16816(o[dt], pal[ks], bv + 0);
                mma16816(o[dt], pal[ks + 1], bv + 2);
            }
        }
        __syncthreads();
    }

    const float inv0 = 1.f / l0, inv1 = 1.f / l1;
    const int b = bh >> 5, h = bh & 7, a3 = (bh >> 3) & 3;
    float* outb = g_tmp + (((size_t)(b * 256 + h * 32)) << 12) + (a3 << 10) + i0;
    const int r0 = wid * 16 + (lane >> 2), r1 = r0 + 8;
#pragma unroll
    for (int dt = 0; dt < 4; dt++) {
        int d = dt * 8 + (lane & 3) * 2;
        outb[((size_t)d << 12) + r0]       = o[dt][0] * inv0;
        outb[((size_t)(d + 1) << 12) + r0] = o[dt][1] * inv0;
        outb[((size_t)d << 12) + r1]       = o[dt][2] * inv1;
        outb[((size_t)(d + 1) << 12) + r1] = o[dt][3] * inv1;
    }
}

// ---------------------------------------------------------------------------
// Kernel 3: pe — reads g_tmp + conv(g_vf), writes split bf16 planes g_th/g_tl.
// grid 1024, block 512, single pass.
// ---------------------------------------------------------------------------
__global__ __launch_bounds__(512) void pe_kernel(const float* __restrict__ wpe,
                                                 const float* __restrict__ bpe) {
    __shared__ float smp[70][72];
    __shared__ float wsm[49];
    const int bc = blockIdx.x, c = bc & 255, t = threadIdx.x;
    const float* src = g_vf + (size_t)bc * 4096;
    if (t < 49) wsm[t] = wpe[c * 49 + t];
    for (int e = t; e < 70 * 70; e += 512) {
        int yy = e / 70, xx = e % 70, y = yy - 3, x = xx - 3;
        float v = 0.f;
        if ((unsigned)y < 64u && (unsigned)x < 64u) v = src[y * 64 + x];
        smp[yy][xx] = v;
    }
    __syncthreads();
    const float bb = bpe[c];
    const float* tsrc = g_tmp + (size_t)bc * 4096;
    const int y = t >> 3, x0 = (t & 7) * 8;
    float acc[8];
#pragma unroll
    for (int j = 0; j < 8; j++) acc[j] = bb;
#pragma unroll
    for (int dy = 0; dy < 7; dy++) {
        float win[16];
        *(float4*)&win[0]  = *(const float4*)&smp[y + dy][x0 + 0];
        *(float4*)&win[4]  = *(const float4*)&smp[y + dy][x0 + 4];
        *(float4*)&win[8]  = *(const float4*)&smp[y + dy][x0 + 8];
        *(float4*)&win[12] = *(const float4*)&smp[y + dy][x0 + 12];
#pragma unroll
        for (int dx = 0; dx < 7; dx++) {
            float wv = wsm[dy * 7 + dx];
#pragma unroll
            for (int j = 0; j < 8; j++) acc[j] += wv * win[j + dx];
        }
    }
    const size_t p = (size_t)bc * 4096 + y * 64 + x0;
    float4 t0 = *(const float4*)&tsrc[y * 64 + x0];
    float4 t1 = *(const float4*)&tsrc[y * 64 + x0 + 4];
    float fin[8] = {acc[0] + t0.x, acc[1] + t0.y, acc[2] + t0.z, acc[3] + t0.w,
                    acc[4] + t1.x, acc[5] + t1.y, acc[6] + t1.z, acc[7] + t1.w};
    uint32_t th[4], tl[4];
#pragma unroll
    for (int m = 0; m < 4; m++) {
        uint2 s = split2(fin[2 * m], fin[2 * m + 1]);
        th[m] = s.x; tl[m] = s.y;
    }
    *(uint4*)&g_th[p] = make_uint4(th[0], th[1], th[2], th[3]);
    *(uint4*)&g_tl[p] = make_uint4(tl[0], tl[1], tl[2], tl[3]);
}

// ---------------------------------------------------------------------------
// Kernel 4: proj via HMMA from bf16 planes. grid (32, 2, 4), dynamic smem.
// ---------------------------------------------------------------------------
__global__ __launch_bounds__(256, 2) void proj_hmma(const float* __restrict__ bias,
                                                    float* __restrict__ out) {
    extern __shared__ __align__(128) uint8_t shm[];
    float c[2][8][4] = {};
    const int b = blockIdx.z;
    gemm_core(c, shm, g_th + (size_t)b * (256 * 4096), g_tl + (size_t)b * (256 * 4096),
              g_wph, g_wpl);

    const int t = threadIdx.x, lane = t & 31, wid = t >> 5;
    const int wm = wid >> 1, wn = wid & 1;
    const int nBase = blockIdx.x * 128, oBase = blockIdx.y * 128;
    const int ncol0 = nBase + wn * 64 + (lane & 3) * 2;
#pragma unroll
    for (int mi = 0; mi < 2; mi++)
#pragma unroll
        for (int half = 0; half < 2; half++) {
            int o = oBase + wm * 32 + mi * 16 + half * 8 + (lane >> 2);
            float bo = bias[o];
            float* orow = out + (((size_t)(b * 256 + o)) << 12);
#pragma unroll
            for (int ni = 0; ni < 8; ni++) {
                int n = ncol0 + ni * 8;
                *(float2*)&orow[n] = make_float2(c[mi][ni][half * 2 + 0] + bo,
                                                 c[mi][ni][half * 2 + 1] + bo);
            }
        }
}

// ---------------------------------------------------------------------------
extern "C" void kernel_launch(void* const* d_in, const int* in_sizes, int n_in,
                              void* d_out, int out_size) {
    const float* x      = (const float*)d_in[0];
    const float* w_qkv  = (const float*)d_in[1];
    const float* b_qkv  = (const float*)d_in[2];
    const float* w_pe   = (const float*)d_in[3];
    const float* b_pe   = (const float*)d_in[4];
    const float* w_proj = (const float*)d_in[5];
    const float* b_proj = (const float*)d_in[6];
    float* out = (float*)d_out;

    cudaFuncSetAttribute(qkv_hmma, cudaFuncAttributeMaxDynamicSharedMemorySize, GSMEM);
    cudaFuncSetAttribute(proj_hmma, cudaFuncAttributeMaxDynamicSharedMemorySize, GSMEM);

    split_w<<<256, 256>>>(w_qkv, w_proj);
    split_x<<<4096, 256>>>(x);
    qkv_hmma<<<dim3(32, 6, 4), 256, GSMEM>>>(b_qkv);
    repack<<<dim3(8, 128), 256>>>();
    attn3<<<dim3(8, 128), 256>>>();
    pe_kernel<<<1024, 512>>>(w_pe, b_pe);
    proj_hmma<<<dim3(32, 2, 4), 256, GSMEM>>>(b_proj, out);
}